// round 15
// baseline (speedup 1.0000x reference)
#include <cuda_runtime.h>
#include <cuda_bf16.h>
#include <math.h>
#include <stdint.h>

#define S     4096
#define CDIM  1280
#define HIDD  128
#define DID   1536
#define EPSV  1e-5f

// ---------------- scratch (static device globals; no allocations) ----------
__device__ float          g_tmean[S];
__device__ float          g_trstd[S];
__device__ __nv_bfloat16  g_ztb [(size_t)S * CDIM];
__device__ __nv_bfloat16  g_wqb [(size_t)HIDD * CDIM];
__device__ __nv_bfloat16  g_wkb [(size_t)HIDD * CDIM];
__device__ __nv_bfloat16  g_wvb [(size_t)HIDD * CDIM];
__device__ __nv_bfloat16  g_wob [(size_t)CDIM * HIDD];
__device__ __nv_bfloat16  g_Qb  [(size_t)S * HIDD];
__device__ __nv_bfloat16  g_Kb  [(size_t)S * HIDD];
__device__ __nv_bfloat16  g_Vb  [(size_t)S * HIDD];
__device__ __nv_bfloat16  g_Vtb [(size_t)HIDD * S];
__device__ float          g_iv  [HIDD];
__device__ float          g_cidp[CDIM];
__device__ float          g_maskv[S];
__device__ __nv_bfloat16  g_qkvp[(size_t)12 * S * HIDD];
__device__ __nv_bfloat16  g_Opart[(size_t)4 * S * HIDD];
__device__ float          g_mpart[4 * S];
__device__ float          g_lpart[4 * S];
__device__ __nv_bfloat16  g_avb [(size_t)S * HIDD];
__device__ float          g_att [(size_t)S * CDIM];
__device__ float          g_wo_sa[10 * S];
__device__ float          g_wo_sq[10 * S];
__device__ float          g_wo_sd[10 * S];
__device__ float          g_wrow[S];
__device__ float          g_mean_f;
__device__ float          g_rstd_f;

// ---------------- helpers ----------------------------------------------------
__device__ __forceinline__ void cp16(void* dst, const void* src) {
    uint32_t d = (uint32_t)__cvta_generic_to_shared(dst);
    asm volatile("cp.async.cg.shared.global [%0], [%1], 16;\n" :: "r"(d), "l"(src));
}
#define CP_COMMIT() asm volatile("cp.async.commit_group;\n" ::: "memory")
#define CP_WAIT1()  asm volatile("cp.async.wait_group 1;\n" ::: "memory")

__device__ __forceinline__ uint32_t saddr(const void* p) {
    return (uint32_t)__cvta_generic_to_shared(p);
}

__device__ __forceinline__ void ldsm_x4(uint32_t& r0, uint32_t& r1, uint32_t& r2,
                                        uint32_t& r3, uint32_t a) {
    asm volatile("ldmatrix.sync.aligned.m8n8.x4.shared.b16 {%0,%1,%2,%3}, [%4];"
                 : "=r"(r0), "=r"(r1), "=r"(r2), "=r"(r3) : "r"(a));
}

__device__ __forceinline__ void mma_bf16(float* d,
        uint32_t a0, uint32_t a1, uint32_t a2, uint32_t a3,
        uint32_t b0, uint32_t b1) {
    asm volatile(
        "mma.sync.aligned.m16n8k16.row.col.f32.bf16.bf16.f32 "
        "{%0,%1,%2,%3}, {%4,%5,%6,%7}, {%8,%9}, {%0,%1,%2,%3};"
        : "+f"(d[0]), "+f"(d[1]), "+f"(d[2]), "+f"(d[3])
        : "r"(a0), "r"(a1), "r"(a2), "r"(a3), "r"(b0), "r"(b1));
}

__device__ __forceinline__ uint32_t pack_bf16(float x, float y) {
    __nv_bfloat162 t = __floats2bfloat162_rn(x, y);
    return *reinterpret_cast<uint32_t*>(&t);
}

__device__ __forceinline__ float2 unpack_bf16(uint32_t u) {
    __nv_bfloat162 t = *reinterpret_cast<__nv_bfloat162*>(&u);
    return make_float2(__bfloat162float(t.x), __bfloat162float(t.y));
}

// ---------------- prep: token LN stats + weight convert + dual matvec --------
__global__ void prep_kernel(const float* __restrict__ z,
                            float* __restrict__ tmean, float* __restrict__ trstd,
                            const float* __restrict__ wq, const float* __restrict__ wk,
                            const float* __restrict__ wv, const float* __restrict__ wo,
                            __nv_bfloat16* qb, __nv_bfloat16* kb,
                            __nv_bfloat16* vb, __nv_bfloat16* ob,
                            const float* __restrict__ w1, const float* __restrict__ b1,
                            const float* __restrict__ w2, const float* __restrict__ b2,
                            const float* __restrict__ x,
                            float* __restrict__ o1, float* __restrict__ o2) {
    __shared__ float ssum[8][33], ssq[8][33];
    __shared__ float sm[256];
    const int blk = blockIdx.x;
    if (blk < 128) {
        const int tok0 = blk * 32;
        const int tok = threadIdx.x & 31, stripe = threadIdx.x >> 5;
        float s = 0.f, q = 0.f;
        for (int c = stripe; c < CDIM; c += 8) {
            float v = z[(size_t)c * S + tok0 + tok];
            s += v; q += v * v;
        }
        ssum[stripe][tok] = s; ssq[stripe][tok] = q;
        __syncthreads();
        if (threadIdx.x < 32) {
            float st = 0.f, qt = 0.f;
            #pragma unroll
            for (int k = 0; k < 8; k++) { st += ssum[k][threadIdx.x]; qt += ssq[k][threadIdx.x]; }
            float mean = st / CDIM;
            float var  = qt / CDIM - mean * mean;
            tmean[tok0 + threadIdx.x] = mean;
            trstd[tok0 + threadIdx.x] = rsqrtf(var + EPSV);
        }
    } else if (blk < 768) {
        const int j = blk - 128;
        const int which = j / 160;
        const int base = (j % 160) * 1024;
        const float* src; __nv_bfloat16* dst;
        if (which == 0)      { src = wq; dst = qb; }
        else if (which == 1) { src = wk; dst = kb; }
        else if (which == 2) { src = wv; dst = vb; }
        else                 { src = wo; dst = ob; }
        #pragma unroll
        for (int r = 0; r < 4; r++) {
            int i = base + r * 256 + threadIdx.x;
            dst[i] = __float2bfloat16(src[i]);
        }
    } else {
        const int n = blk - 768;
        const float* w; float bv; float* o; int nn;
        if (n < HIDD) { nn = n;        w = w1 + (size_t)nn * DID; bv = b1[nn]; o = o1; }
        else          { nn = n - HIDD; w = w2 + (size_t)nn * DID; bv = b2[nn]; o = o2; }
        const float4* w4 = (const float4*)w;
        const float4* x4 = (const float4*)x;
        float s = 0.f;
        for (int k = threadIdx.x; k < DID / 4; k += 256) {
            float4 wv4 = w4[k], xv = x4[k];
            s += wv4.x * xv.x + wv4.y * xv.y + wv4.z * xv.z + wv4.w * xv.w;
        }
        sm[threadIdx.x] = s; __syncthreads();
        for (int off = 128; off > 0; off >>= 1) {
            if (threadIdx.x < off) sm[threadIdx.x] += sm[threadIdx.x + off];
            __syncthreads();
        }
        if (threadIdx.x == 0) o[nn] = sm[0] + bv;
    }
}

// ---------------- fused normalize + transpose: z (C,S) -> ztb (S,C) bf16 -----
__global__ void norm_transpose_kernel(const float* __restrict__ z,
                                      const float* __restrict__ tmean,
                                      const float* __restrict__ trstd,
                                      __nv_bfloat16* __restrict__ ztb) {
    __shared__ float tile[32][33];
    int s0 = blockIdx.x * 32, c0 = blockIdx.y * 32;
    #pragma unroll
    for (int i = threadIdx.y; i < 32; i += 8)
        tile[i][threadIdx.x] = z[(size_t)(c0 + i) * S + s0 + threadIdx.x];
    __syncthreads();
    #pragma unroll
    for (int i = threadIdx.y; i < 32; i += 8) {
        const int tok = s0 + i;
        const float mean = tmean[tok], rstd = trstd[tok];
        ztb[(size_t)tok * CDIM + c0 + threadIdx.x] =
            __float2bfloat16((tile[threadIdx.x][i] - mean) * rstd);
    }
}

// ---------------- bf16 mma GEMM engine (128x128, BT, ldmatrix), bf16 out -----
__device__ __forceinline__ void bf16_gemm_body_bout(
        const __nv_bfloat16* __restrict__ A, const __nv_bfloat16* __restrict__ B,
        __nv_bfloat16* __restrict__ Cb,
        int N, int K, int kstart, int nkt, int m0, int n0) {
    __shared__ uint32_t As[2][128][12];
    __shared__ uint32_t Bs[2][128][12];

    const int tid  = threadIdx.x;
    const int lane = tid & 31, wid = tid >> 5;
    const int g    = lane >> 2, tig = lane & 3;
    const int wm   = (wid >> 2) * 64;
    const int wn   = (wid & 3) * 32;

    const int l7    = lane & 7;
    const int lrow8 = (lane >> 3) & 1;
    const int lcol4 = (lane >> 4) * 4;
    const int quad  = lane >> 3;
    const int brow  = (quad >= 2) ? 8 : 0;
    const int bcol  = (quad & 1) * 4;

    const int fr = tid >> 1, fc = (tid & 1);

    float acc[4][4][4] = {};

    auto fill = [&](int s, int k0) {
        cp16(&As[s][fr][fc * 4], A + (size_t)(m0 + fr) * K + k0 + fc * 8);
        cp16(&Bs[s][fr][fc * 4], B + (size_t)(n0 + fr) * K + k0 + fc * 8);
    };

    fill(0, kstart);
    CP_COMMIT();

    for (int t = 0; t < nkt; t++) {
        const int st = t & 1;
        if (t + 1 < nkt) fill(st ^ 1, kstart + (t + 1) * 16);
        CP_COMMIT();
        CP_WAIT1();
        __syncthreads();

        uint32_t a[4][4], b[4][2];
        #pragma unroll
        for (int mf = 0; mf < 4; mf++)
            ldsm_x4(a[mf][0], a[mf][1], a[mf][2], a[mf][3],
                    saddr(&As[st][wm + mf * 16 + l7 + 8 * lrow8][lcol4]));
        ldsm_x4(b[0][0], b[0][1], b[1][0], b[1][1],
                saddr(&Bs[st][wn + brow + l7][bcol]));
        ldsm_x4(b[2][0], b[2][1], b[3][0], b[3][1],
                saddr(&Bs[st][wn + 16 + brow + l7][bcol]));
        #pragma unroll
        for (int mf = 0; mf < 4; mf++)
            #pragma unroll
            for (int nf = 0; nf < 4; nf++)
                mma_bf16(acc[mf][nf], a[mf][0], a[mf][1], a[mf][2], a[mf][3],
                         b[nf][0], b[nf][1]);
        __syncthreads();
    }

    #pragma unroll
    for (int mf = 0; mf < 4; mf++) {
        #pragma unroll
        for (int nf = 0; nf < 4; nf++) {
            const int r0 = m0 + wm + mf * 16 + g;
            const int c  = n0 + wn + nf * 8 + 2 * tig;
            *(uint32_t*)&Cb[(size_t)r0 * N + c]       = pack_bf16(acc[mf][nf][0], acc[mf][nf][1]);
            *(uint32_t*)&Cb[(size_t)(r0 + 8) * N + c] = pack_bf16(acc[mf][nf][2], acc[mf][nf][3]);
        }
    }
}

// Fused QKV split-K x4 -> bf16 partials: grid (1, 32, 12); z = which*4 + split.
__global__ __launch_bounds__(256, 2)
void qkv_mma_kernel(const __nv_bfloat16* __restrict__ A,
                    const __nv_bfloat16* __restrict__ wq, const __nv_bfloat16* __restrict__ wk,
                    const __nv_bfloat16* __restrict__ wv, __nv_bfloat16* __restrict__ qkvp) {
    const int which = blockIdx.z >> 2;
    const int split = blockIdx.z & 3;
    const __nv_bfloat16* B = (which == 0) ? wq : (which == 1) ? wk : wv;
    __nv_bfloat16* out = qkvp + (size_t)blockIdx.z * S * HIDD;
    bf16_gemm_body_bout(A, B, out, HIDD, CDIM, split * 320, 20,
                        blockIdx.y * 128, blockIdx.x * 128);
}

// WO GEMM with fused decoupling-stats epilogue. grid (10, 32).
__global__ __launch_bounds__(256, 2)
void wo_mma_kernel(const __nv_bfloat16* __restrict__ A, const __nv_bfloat16* __restrict__ B,
                   const float* __restrict__ bias, const float* __restrict__ cidp,
                   float* __restrict__ C,
                   float* __restrict__ sa_p, float* __restrict__ sq_p,
                   float* __restrict__ sd_p) {
    __shared__ uint32_t As[2][128][12];
    __shared__ uint32_t Bs[2][128][12];
    __shared__ float ssa[4][128], ssq2[4][128], ssd[4][128];

    const int N = CDIM, K = HIDD;
    const int m0 = blockIdx.y * 128, n0 = blockIdx.x * 128;
    const int tid  = threadIdx.x;
    const int lane = tid & 31, wid = tid >> 5;
    const int g    = lane >> 2, tig = lane & 3;
    const int wm   = (wid >> 2) * 64;
    const int wn   = (wid & 3) * 32;

    const int l7    = lane & 7;
    const int lrow8 = (lane >> 3) & 1;
    const int lcol4 = (lane >> 4) * 4;
    const int quad  = lane >> 3;
    const int brow  = (quad >= 2) ? 8 : 0;
    const int bcol  = (quad & 1) * 4;

    const int fr = tid >> 1, fc = (tid & 1);

    float acc[4][4][4] = {};

    auto fill = [&](int s, int k0) {
        cp16(&As[s][fr][fc * 4], A + (size_t)(m0 + fr) * K + k0 + fc * 8);
        cp16(&Bs[s][fr][fc * 4], B + (size_t)(n0 + fr) * K + k0 + fc * 8);
    };

    fill(0, 0);
    CP_COMMIT();

    const int nkt = 8;
    for (int t = 0; t < nkt; t++) {
        const int st = t & 1;
        if (t + 1 < nkt) fill(st ^ 1, (t + 1) * 16);
        CP_COMMIT();
        CP_WAIT1();
        __syncthreads();

        uint32_t a[4][4], b[4][2];
        #pragma unroll
        for (int mf = 0; mf < 4; mf++)
            ldsm_x4(a[mf][0], a[mf][1], a[mf][2], a[mf][3],
                    saddr(&As[st][wm + mf * 16 + l7 + 8 * lrow8][lcol4]));
        ldsm_x4(b[0][0], b[0][1], b[1][0], b[1][1],
                saddr(&Bs[st][wn + brow + l7][bcol]));
        ldsm_x4(b[2][0], b[2][1], b[3][0], b[3][1],
                saddr(&Bs[st][wn + 16 + brow + l7][bcol]));
        #pragma unroll
        for (int mf = 0; mf < 4; mf++)
            #pragma unroll
            for (int nf = 0; nf < 4; nf++)
                mma_bf16(acc[mf][nf], a[mf][0], a[mf][1], a[mf][2], a[mf][3],
                         b[nf][0], b[nf][1]);
        __syncthreads();
    }

    float tsa[4][2] = {}, tsq[4][2] = {}, tsd[4][2] = {};
    #pragma unroll
    for (int mf = 0; mf < 4; mf++) {
        #pragma unroll
        for (int nf = 0; nf < 4; nf++) {
            const int r0 = m0 + wm + mf * 16 + g;
            const int c  = n0 + wn + nf * 8 + 2 * tig;
            float b0 = bias[c], b1 = bias[c + 1];
            float c0v = cidp[c], c1v = cidp[c + 1];
            float2 v0 = make_float2(acc[mf][nf][0] + b0, acc[mf][nf][1] + b1);
            float2 v1 = make_float2(acc[mf][nf][2] + b0, acc[mf][nf][3] + b1);
            *(float2*)&C[(size_t)r0 * N + c]       = v0;
            *(float2*)&C[(size_t)(r0 + 8) * N + c] = v1;
            tsa[mf][0] += v0.x + v0.y;
            tsa[mf][1] += v1.x + v1.y;
            tsq[mf][0] += v0.x * v0.x + v0.y * v0.y;
            tsq[mf][1] += v1.x * v1.x + v1.y * v1.y;
            tsd[mf][0] += v0.x * c0v + v0.y * c1v;
            tsd[mf][1] += v1.x * c0v + v1.y * c1v;
        }
    }
    #pragma unroll
    for (int mf = 0; mf < 4; mf++) {
        #pragma unroll
        for (int h = 0; h < 2; h++) {
            float a0 = tsa[mf][h], q0 = tsq[mf][h], d0 = tsd[mf][h];
            #pragma unroll
            for (int o = 1; o <= 2; o <<= 1) {
                a0 += __shfl_xor_sync(0xffffffffu, a0, o);
                q0 += __shfl_xor_sync(0xffffffffu, q0, o);
                d0 += __shfl_xor_sync(0xffffffffu, d0, o);
            }
            if (tig == 0) {
                const int row = wm + mf * 16 + g + h * 8;
                const int cb = wid & 3;
                ssa[cb][row] = a0; ssq2[cb][row] = q0; ssd[cb][row] = d0;
            }
        }
    }
    __syncthreads();
    if (tid < 128) {
        float a0 = ssa[0][tid] + ssa[1][tid] + ssa[2][tid] + ssa[3][tid];
        float q0 = ssq2[0][tid] + ssq2[1][tid] + ssq2[2][tid] + ssq2[3][tid];
        float d0 = ssd[0][tid] + ssd[1][tid] + ssd[2][tid] + ssd[3][tid];
        const int grow = m0 + tid;
        sa_p[blockIdx.x * S + grow] = a0;
        sq_p[blockIdx.x * S + grow] = q0;
        sd_p[blockIdx.x * S + grow] = d0;
    }
}

// Reduce bf16 QKV partials x4 (+bias) -> bf16 Q/K/V; fused mask + V transpose.
__global__ void reduce_qkv_kernel(const __nv_bfloat16* __restrict__ qkvp,
                                  const float* __restrict__ bq, const float* __restrict__ bk,
                                  const float* __restrict__ bv,
                                  const float* __restrict__ iv,
                                  __nv_bfloat16* __restrict__ Qb, __nv_bfloat16* __restrict__ Kb,
                                  __nv_bfloat16* __restrict__ Vb, __nv_bfloat16* __restrict__ Vtb,
                                  float* __restrict__ maskv) {
    __shared__ __nv_bfloat16 vt[128][10];
    const size_t MN = (size_t)S * HIDD;
    const int which = blockIdx.y;
    const int t = threadIdx.x;
    const int lane = t & 31, w = t >> 5;
    const int row = blockIdx.x * 8 + w;
    const int col = lane * 4;
    size_t i = ((size_t)blockIdx.x * 256 + t) * 4;

    const __nv_bfloat16* base = qkvp + (size_t)which * 4 * MN;
    float4 r = make_float4(0.f, 0.f, 0.f, 0.f);
    #pragma unroll
    for (int zp = 0; zp < 4; zp++) {
        uint2 u = *(const uint2*)&base[(size_t)zp * MN + i];
        float2 lo = unpack_bf16(u.x), hi = unpack_bf16(u.y);
        r.x += lo.x; r.y += lo.y; r.z += hi.x; r.w += hi.y;
    }
    const float* bias = (which == 0) ? bq : (which == 1) ? bk : bv;
    float4 bb = *(const float4*)&bias[col];
    r.x += bb.x; r.y += bb.y; r.z += bb.z; r.w += bb.w;
    uint2 packed;
    packed.x = pack_bf16(r.x, r.y);
    packed.y = pack_bf16(r.z, r.w);

    if (which == 0) {
        *(uint2*)&Qb[i] = packed;
    } else if (which == 1) {
        *(uint2*)&Kb[i] = packed;
        float4 ivv = *(const float4*)&iv[col];
        float dot = r.x * ivv.x + r.y * ivv.y + r.z * ivv.z + r.w * ivv.w;
        #pragma unroll
        for (int o = 16; o > 0; o >>= 1)
            dot += __shfl_xor_sync(0xffffffffu, dot, o);
        if (lane == 0) maskv[row] = 1.f / (1.f + expf(-dot));
    } else {
        *(uint2*)&Vb[i] = packed;
        vt[col + 0][w] = __float2bfloat16(r.x);
        vt[col + 1][w] = __float2bfloat16(r.y);
        vt[col + 2][w] = __float2bfloat16(r.z);
        vt[col + 3][w] = __float2bfloat16(r.w);
        __syncthreads();
        if (t < 128) {
            __nv_bfloat16 tmp[8];
            #pragma unroll
            for (int k = 0; k < 8; k++) tmp[k] = vt[t][k];
            *(uint4*)&Vtb[(size_t)t * S + blockIdx.x * 8] = *(uint4*)tmp;
        }
    }
}

// ---------------- flash attention, FA2, 128-row q-tile, 8 warps --------------
// Grid (S/128, 4), 256 threads. Warp w owns rows w*16..w*16+15; KV quarter per
// split (1024 keys, 16 tiles of 64). Softmax state + P in registers.
#define FLASH_SMEM_BYTES (26752 * 4)
__global__ void __launch_bounds__(256, 1)
flash_kernel(const __nv_bfloat16* __restrict__ Qb, const __nv_bfloat16* __restrict__ Kb,
             const __nv_bfloat16* __restrict__ Vtb, const float* __restrict__ maskv,
             __nv_bfloat16* __restrict__ Opart, float* __restrict__ mpart,
             float* __restrict__ lpart) {
    extern __shared__ uint32_t smu[];
    uint32_t* Qs   = smu;               // 128*68 = 8704
    uint32_t* KsB  = smu + 8704;        // 2*4352 = 8704
    uint32_t* VTsB = smu + 17408;       // 2*4608 = 9216
    float* msk = (float*)(smu + 26624); // 2*64

    const int tid  = threadIdx.x;
    const int lane = tid & 31, w = tid >> 5;
    const int g    = lane >> 2, tig = lane & 3;
    const int wm   = w * 16;                    // 0..112

    const int l7    = lane & 7;
    const int lrow8 = (lane >> 3) & 1;
    const int lcol4 = (lane >> 4) * 4;
    const int quad  = lane >> 3;
    const int brow  = (quad >= 2) ? 8 : 0;
    const int bcol  = (quad & 1) * 4;

    const int qbase  = blockIdx.x * 128;
    const int split  = blockIdx.y;
    const int kstart = split * (S / 4);
    const int NT     = (S / 4) / 64;            // 16

    auto fillKV = [&](int st, int kb) {
        #pragma unroll
        for (int i = 0; i < 4; i++) {
            int ci = i * 256 + tid;             // 0..1023
            int kr = ci >> 4, kch = (ci & 15);
            cp16(KsB + st * 4352 + kr * 68 + kch * 4,
                 Kb + (size_t)(kb + kr) * HIDD + kch * 8);
            int vr = ci >> 3, vch = (ci & 7);
            cp16(VTsB + st * 4608 + vr * 36 + vch * 4,
                 Vtb + (size_t)vr * S + kb + vch * 8);
        }
        if (tid < 16) cp16(msk + st * 64 + tid * 4, maskv + kb + tid * 4);
    };

    // prologue: Q (128 rows x 16 chunks = 2048), then KV stage 0
    #pragma unroll
    for (int i = 0; i < 8; i++) {
        int ci = i * 256 + tid;
        int r = ci >> 4, ch = (ci & 15);
        cp16(Qs + r * 68 + ch * 4, Qb + (size_t)(qbase + r) * HIDD + ch * 8);
    }
    CP_COMMIT();
    fillKV(0, kstart);
    CP_COMMIT();
    asm volatile("cp.async.wait_group 1;\n" ::: "memory");
    __syncthreads();

    uint32_t qf[8][4];
    {
        const int qrow = wm + l7 + 8 * lrow8;
        #pragma unroll
        for (int kt = 0; kt < 8; kt++)
            ldsm_x4(qf[kt][0], qf[kt][1], qf[kt][2], qf[kt][3],
                    saddr(&Qs[qrow * 68 + kt * 8 + lcol4]));
    }

    float o_acc[16][4] = {};
    float m0 = -1e30f, m1 = -1e30f, l0 = 0.f, l1 = 0.f;

    for (int t = 0; t < NT; t++) {
        const int st = t & 1;
        if (t + 1 < NT) fillKV(st ^ 1, kstart + (t + 1) * 64);
        CP_COMMIT();
        CP_WAIT1();
        __syncthreads();

        const uint32_t* Ks  = KsB + st * 4352;
        const uint32_t* VTs = VTsB + st * 4608;
        const float* mk = msk + st * 64;

        float s_acc[8][4] = {};
        #pragma unroll
        for (int kt = 0; kt < 8; kt++) {
            uint32_t b[8][2];
            #pragma unroll
            for (int nb = 0; nb < 4; nb++)
                ldsm_x4(b[2 * nb][0], b[2 * nb][1], b[2 * nb + 1][0], b[2 * nb + 1][1],
                        saddr(&Ks[(nb * 16 + brow + l7) * 68 + kt * 8 + bcol]));
            #pragma unroll
            for (int nf = 0; nf < 8; nf++)
                mma_bf16(s_acc[nf], qf[kt][0], qf[kt][1], qf[kt][2], qf[kt][3],
                         b[nf][0], b[nf][1]);
        }

        float rmax0 = -1e30f, rmax1 = -1e30f;
        #pragma unroll
        for (int nf = 0; nf < 8; nf++) {
            const int cc = nf * 8 + 2 * tig;
            const float mk0 = mk[cc] * 0.015625f, mk1 = mk[cc + 1] * 0.015625f;
            s_acc[nf][0] *= mk0; s_acc[nf][1] *= mk1;
            s_acc[nf][2] *= mk0; s_acc[nf][3] *= mk1;
            rmax0 = fmaxf(rmax0, fmaxf(s_acc[nf][0], s_acc[nf][1]));
            rmax1 = fmaxf(rmax1, fmaxf(s_acc[nf][2], s_acc[nf][3]));
        }
        #pragma unroll
        for (int o = 1; o <= 2; o <<= 1) {
            rmax0 = fmaxf(rmax0, __shfl_xor_sync(0xffffffffu, rmax0, o));
            rmax1 = fmaxf(rmax1, __shfl_xor_sync(0xffffffffu, rmax1, o));
        }
        const float mn0 = fmaxf(m0, rmax0), mn1 = fmaxf(m1, rmax1);
        const float c0 = __expf(m0 - mn0), c1 = __expf(m1 - mn1);
        m0 = mn0; m1 = mn1;

        uint32_t pa[4][4];
        float ps0 = 0.f, ps1 = 0.f;
        #pragma unroll
        for (int k2 = 0; k2 < 4; k2++) {
            float p00 = __expf(s_acc[2 * k2][0] - mn0), p01 = __expf(s_acc[2 * k2][1] - mn0);
            float p02 = __expf(s_acc[2 * k2][2] - mn1), p03 = __expf(s_acc[2 * k2][3] - mn1);
            float p10 = __expf(s_acc[2 * k2 + 1][0] - mn0), p11 = __expf(s_acc[2 * k2 + 1][1] - mn0);
            float p12 = __expf(s_acc[2 * k2 + 1][2] - mn1), p13 = __expf(s_acc[2 * k2 + 1][3] - mn1);
            ps0 += p00 + p01 + p10 + p11;
            ps1 += p02 + p03 + p12 + p13;
            pa[k2][0] = pack_bf16(p00, p01);
            pa[k2][1] = pack_bf16(p02, p03);
            pa[k2][2] = pack_bf16(p10, p11);
            pa[k2][3] = pack_bf16(p12, p13);
        }
        #pragma unroll
        for (int o = 1; o <= 2; o <<= 1) {
            ps0 += __shfl_xor_sync(0xffffffffu, ps0, o);
            ps1 += __shfl_xor_sync(0xffffffffu, ps1, o);
        }
        l0 = l0 * c0 + ps0;
        l1 = l1 * c1 + ps1;

        #pragma unroll
        for (int nf = 0; nf < 16; nf++) {
            o_acc[nf][0] *= c0; o_acc[nf][1] *= c0;
            o_acc[nf][2] *= c1; o_acc[nf][3] *= c1;
        }

        #pragma unroll
        for (int k2 = 0; k2 < 4; k2++) {
            #pragma unroll
            for (int np = 0; np < 8; np++) {
                uint32_t b0, b1, b2, b3;
                ldsm_x4(b0, b1, b2, b3,
                        saddr(&VTs[(np * 16 + brow + l7) * 36 + k2 * 8 + bcol]));
                mma_bf16(o_acc[2 * np],     pa[k2][0], pa[k2][1], pa[k2][2], pa[k2][3], b0, b1);
                mma_bf16(o_acc[2 * np + 1], pa[k2][0], pa[k2][1], pa[k2][2], pa[k2][3], b2, b3);
            }
        }
        __syncthreads();
    }

    __nv_bfloat16* Ob = Opart + ((size_t)split * S + qbase) * HIDD;
    const int row0 = wm + g, row1 = wm + g + 8;
    #pragma unroll
    for (int nf = 0; nf < 16; nf++) {
        const int cc = nf * 8 + 2 * tig;
        *(uint32_t*)&Ob[(size_t)row0 * HIDD + cc] = pack_bf16(o_acc[nf][0], o_acc[nf][1]);
        *(uint32_t*)&Ob[(size_t)row1 * HIDD + cc] = pack_bf16(o_acc[nf][2], o_acc[nf][3]);
    }
    if (tig == 0) {
        mpart[split * S + qbase + row0] = m0;
        lpart[split * S + qbase + row0] = l0;
        mpart[split * S + qbase + row1] = m1;
        lpart[split * S + qbase + row1] = l1;
    }
}

// ---------------- combine the 4 KV-split partials -> bf16 av -----------------
__global__ void combine_kernel(const __nv_bfloat16* __restrict__ Opart,
                               const float* __restrict__ mpart,
                               const float* __restrict__ lpart,
                               __nv_bfloat16* __restrict__ avb) {
    const int row = blockIdx.x, col = threadIdx.x;
    float M = -1e30f;
    #pragma unroll
    for (int z = 0; z < 4; z++) M = fmaxf(M, mpart[z * S + row]);
    float denom = 0.f, v = 0.f;
    #pragma unroll
    for (int z = 0; z < 4; z++) {
        const float e = __expf(mpart[z * S + row] - M);
        denom += e * lpart[z * S + row];
        v     += e * __bfloat162float(Opart[((size_t)z * S + row) * HIDD + col]);
    }
    avb[(size_t)row * HIDD + col] = __float2bfloat16(v / denom);
}

// ---------------- fused w + per-row + global LN stats (one block) ------------
__global__ void stats_kernel(const float* __restrict__ sa_p, const float* __restrict__ sq_p,
                             const float* __restrict__ sd_p, const float* __restrict__ cidp,
                             float* __restrict__ wrow) {
    __shared__ float rc[1024], rc2[1024];
    __shared__ double rs[1024], rq[1024];
    // cidp sums
    float s = 0.f, q = 0.f;
    for (int i = threadIdx.x; i < CDIM; i += 1024) {
        float v = cidp[i];
        s += v; q += v * v;
    }
    rc[threadIdx.x] = s; rc2[threadIdx.x] = q; __syncthreads();
    for (int o = 512; o > 0; o >>= 1) {
        if (threadIdx.x < o) { rc[threadIdx.x] += rc[threadIdx.x + o]; rc2[threadIdx.x] += rc2[threadIdx.x + o]; }
        __syncthreads();
    }
    const float sc = rc[0], sc2 = rc2[0];
    __syncthreads();
    // per-row w + stats, accumulate global sums
    double ds = 0.0, dq = 0.0;
    for (int row = threadIdx.x; row < S; row += 1024) {
        float sa = 0.f, sq = 0.f, sd = 0.f;
        #pragma unroll
        for (int nb = 0; nb < 10; nb++) {
            sa += sa_p[nb * S + row];
            sq += sq_p[nb * S + row];
            sd += sd_p[nb * S + row];
        }
        const float wv = 1.f / (1.f + expf(-sd));
        wrow[row] = wv;
        ds += (double)(sa - wv * sc);
        dq += (double)(sq - 2.f * wv * sd + wv * wv * sc2);
    }
    rs[threadIdx.x] = ds; rq[threadIdx.x] = dq; __syncthreads();
    for (int o = 512; o > 0; o >>= 1) {
        if (threadIdx.x < o) { rs[threadIdx.x] += rs[threadIdx.x + o]; rq[threadIdx.x] += rq[threadIdx.x + o]; }
        __syncthreads();
    }
    if (threadIdx.x == 0) {
        double n = (double)S * (double)CDIM;
        double mean = rs[0] / n;
        double var  = rq[0] / n - mean * mean;
        g_mean_f = (float)mean;
        g_rstd_f = (float)rsqrt(var + 1e-5);
    }
}

// ---------------- apply decoupling + normalize + transpose -------------------
__global__ void out_transpose_kernel(const float* __restrict__ att,
                                     const float* __restrict__ wrow,
                                     const float* __restrict__ cidp,
                                     float* __restrict__ out) {
    __shared__ float tile[32][33];
    __shared__ float ws[32];
    float mean = g_mean_f, rstd = g_rstd_f;
    int c0 = blockIdx.x * 32, s0 = blockIdx.y * 32;
    if (threadIdx.y == 0) ws[threadIdx.x] = wrow[s0 + threadIdx.x];
    #pragma unroll
    for (int i = threadIdx.y; i < 32; i += 8)
        tile[i][threadIdx.x] = att[(size_t)(s0 + i) * CDIM + c0 + threadIdx.x];
    __syncthreads();
    #pragma unroll
    for (int i = threadIdx.y; i < 32; i += 8) {
        const float cv = cidp[c0 + i];
        out[(size_t)(c0 + i) * S + s0 + threadIdx.x] =
            (tile[threadIdx.x][i] - ws[threadIdx.x] * cv - mean) * rstd;
    }
}

// ---------------- launch ------------------------------------------------------
extern "C" void kernel_launch(void* const* d_in, const int* in_sizes, int n_in,
                              void* d_out, int out_size) {
    const float* z      = (const float*)d_in[0];
    const float* cid    = (const float*)d_in[1];
    const float* mlp_w  = (const float*)d_in[2];
    const float* mlp_b  = (const float*)d_in[3];
    const float* proj_w = (const float*)d_in[4];
    const float* proj_b = (const float*)d_in[5];
    const float* wq_w   = (const float*)d_in[6];
    const float* wq_b   = (const float*)d_in[7];
    const float* wk_w   = (const float*)d_in[8];
    const float* wk_b   = (const float*)d_in[9];
    const float* wv_w   = (const float*)d_in[10];
    const float* wv_b   = (const float*)d_in[11];
    const float* wo_w   = (const float*)d_in[12];
    const float* wo_b   = (const float*)d_in[13];
    float* out = (float*)d_out;

    float *tmean, *trstd, *iv, *cidp, *maskv, *mpart, *lpart, *att;
    float *wo_sa, *wo_sq, *wo_sd, *wrow;
    __nv_bfloat16 *ztb, *wqb, *wkb, *wvb, *wob, *Qb, *Kb, *Vb, *Vtb, *avb, *qkvp, *Opart;
    cudaGetSymbolAddress((void**)&tmean, g_tmean);
    cudaGetSymbolAddress((void**)&trstd, g_trstd);
    cudaGetSymbolAddress((void**)&ztb,   g_ztb);
    cudaGetSymbolAddress((void**)&wqb,   g_wqb);
    cudaGetSymbolAddress((void**)&wkb,   g_wkb);
    cudaGetSymbolAddress((void**)&wvb,   g_wvb);
    cudaGetSymbolAddress((void**)&wob,   g_wob);
    cudaGetSymbolAddress((void**)&Qb,    g_Qb);
    cudaGetSymbolAddress((void**)&Kb,    g_Kb);
    cudaGetSymbolAddress((void**)&Vb,    g_Vb);
    cudaGetSymbolAddress((void**)&Vtb,   g_Vtb);
    cudaGetSymbolAddress((void**)&iv,    g_iv);
    cudaGetSymbolAddress((void**)&cidp,  g_cidp);
    cudaGetSymbolAddress((void**)&maskv, g_maskv);
    cudaGetSymbolAddress((void**)&qkvp,  g_qkvp);
    cudaGetSymbolAddress((void**)&Opart, g_Opart);
    cudaGetSymbolAddress((void**)&mpart, g_mpart);
    cudaGetSymbolAddress((void**)&lpart, g_lpart);
    cudaGetSymbolAddress((void**)&avb,   g_avb);
    cudaGetSymbolAddress((void**)&att,   g_att);
    cudaGetSymbolAddress((void**)&wo_sa, g_wo_sa);
    cudaGetSymbolAddress((void**)&wo_sq, g_wo_sq);
    cudaGetSymbolAddress((void**)&wo_sd, g_wo_sd);
    cudaGetSymbolAddress((void**)&wrow,  g_wrow);

    static int s_attr_set = 0;
    if (!s_attr_set) {
        cudaFuncSetAttribute(flash_kernel, cudaFuncAttributeMaxDynamicSharedMemorySize,
                             FLASH_SMEM_BYTES);
        s_attr_set = 1;
    }

    dim3 t32x8(32, 8);

    // 1. prep: token LN stats + weight convert + iv/cidp (one launch)
    prep_kernel<<<2176, 256>>>(z, tmean, trstd,
                               wq_w, wk_w, wv_w, wo_w, wqb, wkb, wvb, wob,
                               mlp_w, mlp_b, proj_w, proj_b, cid, iv, cidp);
    // 2. fused normalize + transpose -> bf16 tokens
    norm_transpose_kernel<<<dim3(S / 32, CDIM / 32), t32x8>>>(z, tmean, trstd, ztb);
    // 3. QKV bf16 mma, split-K x4, bf16 partials
    qkv_mma_kernel<<<dim3(1, S / 128, 12), 256>>>(ztb, wqb, wkb, wvb, qkvp);
    // 4. reduce partials + bias -> Q/K/V bf16, fused mask + V-transpose
    reduce_qkv_kernel<<<dim3(512, 3), 256>>>(qkvp, wq_b, wk_b, wv_b, iv,
                                             Qb, Kb, Vb, Vtb, maskv);
    // 5. flash attention (128-row q-tile, 8 warps), grid (32,4)
    flash_kernel<<<dim3(S / 128, 4), 256, FLASH_SMEM_BYTES>>>(
        Qb, Kb, Vtb, maskv, Opart, mpart, lpart);
    // 6. combine splits -> bf16 av
    combine_kernel<<<S, HIDD>>>(Opart, mpart, lpart, avb);
    // 7. attended = av wo^T + wo_b, fused per-row stats partials
    wo_mma_kernel<<<dim3(CDIM / 128, S / 128), 256>>>(avb, wob, wo_b, cidp, att,
                                                      wo_sa, wo_sq, wo_sd);
    // 8. fused w + per-row + global LN stats (one block)
    stats_kernel<<<1, 1024>>>(wo_sa, wo_sq, wo_sd, cidp, wrow);
    // 9. decoupling + normalize + transpose to (C,H,W)
    out_transpose_kernel<<<dim3(CDIM / 32, S / 32), t32x8>>>(att, wrow, cidp, out);
}

// round 16
// speedup vs baseline: 1.0122x; 1.0122x over previous
#include <cuda_runtime.h>
#include <cuda_bf16.h>
#include <math.h>
#include <stdint.h>

#define S     4096
#define CDIM  1280
#define HIDD  128
#define DID   1536
#define EPSV  1e-5f

// ---------------- scratch (static device globals; no allocations) ----------
__device__ float          g_tmean[S];
__device__ float          g_trstd[S];
__device__ __nv_bfloat16  g_ztb [(size_t)S * CDIM];
__device__ __nv_bfloat16  g_wqb [(size_t)HIDD * CDIM];
__device__ __nv_bfloat16  g_wkb [(size_t)HIDD * CDIM];
__device__ __nv_bfloat16  g_wvb [(size_t)HIDD * CDIM];
__device__ __nv_bfloat16  g_wob [(size_t)CDIM * HIDD];
__device__ __nv_bfloat16  g_Qb  [(size_t)S * HIDD];
__device__ __nv_bfloat16  g_Kb  [(size_t)S * HIDD];
__device__ __nv_bfloat16  g_Vtb [(size_t)HIDD * S];
__device__ float          g_iv  [HIDD];
__device__ float          g_cidp[CDIM];
__device__ float          g_maskv[S];
__device__ __nv_bfloat16  g_qkvp[(size_t)12 * S * HIDD];
__device__ __nv_bfloat16  g_Opart[(size_t)4 * S * HIDD];
__device__ float          g_mpart[4 * S];
__device__ float          g_lpart[4 * S];
__device__ __nv_bfloat16  g_avb [(size_t)S * HIDD];
__device__ float          g_att [(size_t)S * CDIM];
__device__ float          g_wo_sa[10 * S];
__device__ float          g_wo_sq[10 * S];
__device__ float          g_wo_sd[10 * S];
__device__ float          g_wrow[S];
__device__ float          g_mean_f;
__device__ float          g_rstd_f;

// ---------------- helpers ----------------------------------------------------
__device__ __forceinline__ void cp16(void* dst, const void* src) {
    uint32_t d = (uint32_t)__cvta_generic_to_shared(dst);
    asm volatile("cp.async.cg.shared.global [%0], [%1], 16;\n" :: "r"(d), "l"(src));
}
#define CP_COMMIT() asm volatile("cp.async.commit_group;\n" ::: "memory")
#define CP_WAIT1()  asm volatile("cp.async.wait_group 1;\n" ::: "memory")

__device__ __forceinline__ uint32_t saddr(const void* p) {
    return (uint32_t)__cvta_generic_to_shared(p);
}

__device__ __forceinline__ void ldsm_x4(uint32_t& r0, uint32_t& r1, uint32_t& r2,
                                        uint32_t& r3, uint32_t a) {
    asm volatile("ldmatrix.sync.aligned.m8n8.x4.shared.b16 {%0,%1,%2,%3}, [%4];"
                 : "=r"(r0), "=r"(r1), "=r"(r2), "=r"(r3) : "r"(a));
}

__device__ __forceinline__ void mma_bf16(float* d,
        uint32_t a0, uint32_t a1, uint32_t a2, uint32_t a3,
        uint32_t b0, uint32_t b1) {
    asm volatile(
        "mma.sync.aligned.m16n8k16.row.col.f32.bf16.bf16.f32 "
        "{%0,%1,%2,%3}, {%4,%5,%6,%7}, {%8,%9}, {%0,%1,%2,%3};"
        : "+f"(d[0]), "+f"(d[1]), "+f"(d[2]), "+f"(d[3])
        : "r"(a0), "r"(a1), "r"(a2), "r"(a3), "r"(b0), "r"(b1));
}

__device__ __forceinline__ uint32_t pack_bf16(float x, float y) {
    __nv_bfloat162 t = __floats2bfloat162_rn(x, y);
    return *reinterpret_cast<uint32_t*>(&t);
}

__device__ __forceinline__ float2 unpack_bf16(uint32_t u) {
    __nv_bfloat162 t = *reinterpret_cast<__nv_bfloat162*>(&u);
    return make_float2(__bfloat162float(t.x), __bfloat162float(t.y));
}

// ---------------- prep: token LN stats + weight convert + dual matvec --------
__global__ void prep_kernel(const float* __restrict__ z,
                            float* __restrict__ tmean, float* __restrict__ trstd,
                            const float* __restrict__ wq, const float* __restrict__ wk,
                            const float* __restrict__ wv, const float* __restrict__ wo,
                            __nv_bfloat16* qb, __nv_bfloat16* kb,
                            __nv_bfloat16* vb, __nv_bfloat16* ob,
                            const float* __restrict__ w1, const float* __restrict__ b1,
                            const float* __restrict__ w2, const float* __restrict__ b2,
                            const float* __restrict__ x,
                            float* __restrict__ o1, float* __restrict__ o2) {
    __shared__ float ssum[8][33], ssq[8][33];
    __shared__ float sm[256];
    const int blk = blockIdx.x;
    if (blk < 128) {
        const int tok0 = blk * 32;
        const int tok = threadIdx.x & 31, stripe = threadIdx.x >> 5;
        float s = 0.f, q = 0.f;
        for (int c = stripe; c < CDIM; c += 8) {
            float v = z[(size_t)c * S + tok0 + tok];
            s += v; q += v * v;
        }
        ssum[stripe][tok] = s; ssq[stripe][tok] = q;
        __syncthreads();
        if (threadIdx.x < 32) {
            float st = 0.f, qt = 0.f;
            #pragma unroll
            for (int k = 0; k < 8; k++) { st += ssum[k][threadIdx.x]; qt += ssq[k][threadIdx.x]; }
            float mean = st / CDIM;
            float var  = qt / CDIM - mean * mean;
            tmean[tok0 + threadIdx.x] = mean;
            trstd[tok0 + threadIdx.x] = rsqrtf(var + EPSV);
        }
    } else if (blk < 768) {
        const int j = blk - 128;
        const int which = j / 160;
        const int base = (j % 160) * 1024;
        const float* src; __nv_bfloat16* dst;
        if (which == 0)      { src = wq; dst = qb; }
        else if (which == 1) { src = wk; dst = kb; }
        else if (which == 2) { src = wv; dst = vb; }
        else                 { src = wo; dst = ob; }
        #pragma unroll
        for (int r = 0; r < 4; r++) {
            int i = base + r * 256 + threadIdx.x;
            dst[i] = __float2bfloat16(src[i]);
        }
    } else {
        const int n = blk - 768;
        const float* w; float bv; float* o; int nn;
        if (n < HIDD) { nn = n;        w = w1 + (size_t)nn * DID; bv = b1[nn]; o = o1; }
        else          { nn = n - HIDD; w = w2 + (size_t)nn * DID; bv = b2[nn]; o = o2; }
        const float4* w4 = (const float4*)w;
        const float4* x4 = (const float4*)x;
        float s = 0.f;
        for (int k = threadIdx.x; k < DID / 4; k += 256) {
            float4 wv4 = w4[k], xv = x4[k];
            s += wv4.x * xv.x + wv4.y * xv.y + wv4.z * xv.z + wv4.w * xv.w;
        }
        sm[threadIdx.x] = s; __syncthreads();
        for (int off = 128; off > 0; off >>= 1) {
            if (threadIdx.x < off) sm[threadIdx.x] += sm[threadIdx.x + off];
            __syncthreads();
        }
        if (threadIdx.x == 0) o[nn] = sm[0] + bv;
    }
}

// ---------------- fused normalize + transpose: z (C,S) -> ztb (S,C) bf16 -----
__global__ void norm_transpose_kernel(const float* __restrict__ z,
                                      const float* __restrict__ tmean,
                                      const float* __restrict__ trstd,
                                      __nv_bfloat16* __restrict__ ztb) {
    __shared__ float tile[32][33];
    int s0 = blockIdx.x * 32, c0 = blockIdx.y * 32;
    #pragma unroll
    for (int i = threadIdx.y; i < 32; i += 8)
        tile[i][threadIdx.x] = z[(size_t)(c0 + i) * S + s0 + threadIdx.x];
    __syncthreads();
    #pragma unroll
    for (int i = threadIdx.y; i < 32; i += 8) {
        const int tok = s0 + i;
        const float mean = tmean[tok], rstd = trstd[tok];
        ztb[(size_t)tok * CDIM + c0 + threadIdx.x] =
            __float2bfloat16((tile[threadIdx.x][i] - mean) * rstd);
    }
}

// ---------------- bf16 mma GEMM engine (128x128, BT, ldmatrix), bf16 out -----
__device__ __forceinline__ void bf16_gemm_body_bout(
        const __nv_bfloat16* __restrict__ A, const __nv_bfloat16* __restrict__ B,
        __nv_bfloat16* __restrict__ Cb,
        int N, int K, int kstart, int nkt, int m0, int n0) {
    __shared__ uint32_t As[2][128][12];
    __shared__ uint32_t Bs[2][128][12];

    const int tid  = threadIdx.x;
    const int lane = tid & 31, wid = tid >> 5;
    const int g    = lane >> 2, tig = lane & 3;
    const int wm   = (wid >> 2) * 64;
    const int wn   = (wid & 3) * 32;

    const int l7    = lane & 7;
    const int lrow8 = (lane >> 3) & 1;
    const int lcol4 = (lane >> 4) * 4;
    const int quad  = lane >> 3;
    const int brow  = (quad >= 2) ? 8 : 0;
    const int bcol  = (quad & 1) * 4;

    const int fr = tid >> 1, fc = (tid & 1);

    float acc[4][4][4] = {};

    auto fill = [&](int s, int k0) {
        cp16(&As[s][fr][fc * 4], A + (size_t)(m0 + fr) * K + k0 + fc * 8);
        cp16(&Bs[s][fr][fc * 4], B + (size_t)(n0 + fr) * K + k0 + fc * 8);
    };

    fill(0, kstart);
    CP_COMMIT();

    for (int t = 0; t < nkt; t++) {
        const int st = t & 1;
        if (t + 1 < nkt) fill(st ^ 1, kstart + (t + 1) * 16);
        CP_COMMIT();
        CP_WAIT1();
        __syncthreads();

        uint32_t a[4][4], b[4][2];
        #pragma unroll
        for (int mf = 0; mf < 4; mf++)
            ldsm_x4(a[mf][0], a[mf][1], a[mf][2], a[mf][3],
                    saddr(&As[st][wm + mf * 16 + l7 + 8 * lrow8][lcol4]));
        ldsm_x4(b[0][0], b[0][1], b[1][0], b[1][1],
                saddr(&Bs[st][wn + brow + l7][bcol]));
        ldsm_x4(b[2][0], b[2][1], b[3][0], b[3][1],
                saddr(&Bs[st][wn + 16 + brow + l7][bcol]));
        #pragma unroll
        for (int mf = 0; mf < 4; mf++)
            #pragma unroll
            for (int nf = 0; nf < 4; nf++)
                mma_bf16(acc[mf][nf], a[mf][0], a[mf][1], a[mf][2], a[mf][3],
                         b[nf][0], b[nf][1]);
        __syncthreads();
    }

    #pragma unroll
    for (int mf = 0; mf < 4; mf++) {
        #pragma unroll
        for (int nf = 0; nf < 4; nf++) {
            const int r0 = m0 + wm + mf * 16 + g;
            const int c  = n0 + wn + nf * 8 + 2 * tig;
            *(uint32_t*)&Cb[(size_t)r0 * N + c]       = pack_bf16(acc[mf][nf][0], acc[mf][nf][1]);
            *(uint32_t*)&Cb[(size_t)(r0 + 8) * N + c] = pack_bf16(acc[mf][nf][2], acc[mf][nf][3]);
        }
    }
}

// Fused QKV split-K x4 -> bf16 partials: grid (1, 32, 12); z = which*4 + split.
__global__ __launch_bounds__(256, 2)
void qkv_mma_kernel(const __nv_bfloat16* __restrict__ A,
                    const __nv_bfloat16* __restrict__ wq, const __nv_bfloat16* __restrict__ wk,
                    const __nv_bfloat16* __restrict__ wv, __nv_bfloat16* __restrict__ qkvp) {
    const int which = blockIdx.z >> 2;
    const int split = blockIdx.z & 3;
    const __nv_bfloat16* B = (which == 0) ? wq : (which == 1) ? wk : wv;
    __nv_bfloat16* out = qkvp + (size_t)blockIdx.z * S * HIDD;
    bf16_gemm_body_bout(A, B, out, HIDD, CDIM, split * 320, 20,
                        blockIdx.y * 128, blockIdx.x * 128);
}

// WO GEMM with fused decoupling-stats epilogue. grid (10, 32).
__global__ __launch_bounds__(256, 2)
void wo_mma_kernel(const __nv_bfloat16* __restrict__ A, const __nv_bfloat16* __restrict__ B,
                   const float* __restrict__ bias, const float* __restrict__ cidp,
                   float* __restrict__ C,
                   float* __restrict__ sa_p, float* __restrict__ sq_p,
                   float* __restrict__ sd_p) {
    __shared__ uint32_t As[2][128][12];
    __shared__ uint32_t Bs[2][128][12];
    __shared__ float ssa[4][128], ssq2[4][128], ssd[4][128];

    const int N = CDIM, K = HIDD;
    const int m0 = blockIdx.y * 128, n0 = blockIdx.x * 128;
    const int tid  = threadIdx.x;
    const int lane = tid & 31, wid = tid >> 5;
    const int g    = lane >> 2, tig = lane & 3;
    const int wm   = (wid >> 2) * 64;
    const int wn   = (wid & 3) * 32;

    const int l7    = lane & 7;
    const int lrow8 = (lane >> 3) & 1;
    const int lcol4 = (lane >> 4) * 4;
    const int quad  = lane >> 3;
    const int brow  = (quad >= 2) ? 8 : 0;
    const int bcol  = (quad & 1) * 4;

    const int fr = tid >> 1, fc = (tid & 1);

    float acc[4][4][4] = {};

    auto fill = [&](int s, int k0) {
        cp16(&As[s][fr][fc * 4], A + (size_t)(m0 + fr) * K + k0 + fc * 8);
        cp16(&Bs[s][fr][fc * 4], B + (size_t)(n0 + fr) * K + k0 + fc * 8);
    };

    fill(0, 0);
    CP_COMMIT();

    const int nkt = 8;
    for (int t = 0; t < nkt; t++) {
        const int st = t & 1;
        if (t + 1 < nkt) fill(st ^ 1, (t + 1) * 16);
        CP_COMMIT();
        CP_WAIT1();
        __syncthreads();

        uint32_t a[4][4], b[4][2];
        #pragma unroll
        for (int mf = 0; mf < 4; mf++)
            ldsm_x4(a[mf][0], a[mf][1], a[mf][2], a[mf][3],
                    saddr(&As[st][wm + mf * 16 + l7 + 8 * lrow8][lcol4]));
        ldsm_x4(b[0][0], b[0][1], b[1][0], b[1][1],
                saddr(&Bs[st][wn + brow + l7][bcol]));
        ldsm_x4(b[2][0], b[2][1], b[3][0], b[3][1],
                saddr(&Bs[st][wn + 16 + brow + l7][bcol]));
        #pragma unroll
        for (int mf = 0; mf < 4; mf++)
            #pragma unroll
            for (int nf = 0; nf < 4; nf++)
                mma_bf16(acc[mf][nf], a[mf][0], a[mf][1], a[mf][2], a[mf][3],
                         b[nf][0], b[nf][1]);
        __syncthreads();
    }

    float tsa[4][2] = {}, tsq[4][2] = {}, tsd[4][2] = {};
    #pragma unroll
    for (int mf = 0; mf < 4; mf++) {
        #pragma unroll
        for (int nf = 0; nf < 4; nf++) {
            const int r0 = m0 + wm + mf * 16 + g;
            const int c  = n0 + wn + nf * 8 + 2 * tig;
            float b0 = bias[c], b1 = bias[c + 1];
            float c0v = cidp[c], c1v = cidp[c + 1];
            float2 v0 = make_float2(acc[mf][nf][0] + b0, acc[mf][nf][1] + b1);
            float2 v1 = make_float2(acc[mf][nf][2] + b0, acc[mf][nf][3] + b1);
            *(float2*)&C[(size_t)r0 * N + c]       = v0;
            *(float2*)&C[(size_t)(r0 + 8) * N + c] = v1;
            tsa[mf][0] += v0.x + v0.y;
            tsa[mf][1] += v1.x + v1.y;
            tsq[mf][0] += v0.x * v0.x + v0.y * v0.y;
            tsq[mf][1] += v1.x * v1.x + v1.y * v1.y;
            tsd[mf][0] += v0.x * c0v + v0.y * c1v;
            tsd[mf][1] += v1.x * c0v + v1.y * c1v;
        }
    }
    #pragma unroll
    for (int mf = 0; mf < 4; mf++) {
        #pragma unroll
        for (int h = 0; h < 2; h++) {
            float a0 = tsa[mf][h], q0 = tsq[mf][h], d0 = tsd[mf][h];
            #pragma unroll
            for (int o = 1; o <= 2; o <<= 1) {
                a0 += __shfl_xor_sync(0xffffffffu, a0, o);
                q0 += __shfl_xor_sync(0xffffffffu, q0, o);
                d0 += __shfl_xor_sync(0xffffffffu, d0, o);
            }
            if (tig == 0) {
                const int row = wm + mf * 16 + g + h * 8;
                const int cb = wid & 3;
                ssa[cb][row] = a0; ssq2[cb][row] = q0; ssd[cb][row] = d0;
            }
        }
    }
    __syncthreads();
    if (tid < 128) {
        float a0 = ssa[0][tid] + ssa[1][tid] + ssa[2][tid] + ssa[3][tid];
        float q0 = ssq2[0][tid] + ssq2[1][tid] + ssq2[2][tid] + ssq2[3][tid];
        float d0 = ssd[0][tid] + ssd[1][tid] + ssd[2][tid] + ssd[3][tid];
        const int grow = m0 + tid;
        sa_p[blockIdx.x * S + grow] = a0;
        sq_p[blockIdx.x * S + grow] = q0;
        sd_p[blockIdx.x * S + grow] = d0;
    }
}

// Reduce bf16 QKV partials x4 (+bias) -> bf16 Q/K + Vt; fused mask.
__global__ void reduce_qkv_kernel(const __nv_bfloat16* __restrict__ qkvp,
                                  const float* __restrict__ bq, const float* __restrict__ bk,
                                  const float* __restrict__ bv,
                                  const float* __restrict__ iv,
                                  __nv_bfloat16* __restrict__ Qb, __nv_bfloat16* __restrict__ Kb,
                                  __nv_bfloat16* __restrict__ Vtb,
                                  float* __restrict__ maskv) {
    __shared__ __nv_bfloat16 vt[128][10];
    const size_t MN = (size_t)S * HIDD;
    const int which = blockIdx.y;
    const int t = threadIdx.x;
    const int lane = t & 31, w = t >> 5;
    const int row = blockIdx.x * 8 + w;
    const int col = lane * 4;
    size_t i = ((size_t)blockIdx.x * 256 + t) * 4;

    const __nv_bfloat16* base = qkvp + (size_t)which * 4 * MN;
    float4 r = make_float4(0.f, 0.f, 0.f, 0.f);
    #pragma unroll
    for (int zp = 0; zp < 4; zp++) {
        uint2 u = *(const uint2*)&base[(size_t)zp * MN + i];
        float2 lo = unpack_bf16(u.x), hi = unpack_bf16(u.y);
        r.x += lo.x; r.y += lo.y; r.z += hi.x; r.w += hi.y;
    }
    const float* bias = (which == 0) ? bq : (which == 1) ? bk : bv;
    float4 bb = *(const float4*)&bias[col];
    r.x += bb.x; r.y += bb.y; r.z += bb.z; r.w += bb.w;

    if (which == 0) {
        uint2 packed;
        packed.x = pack_bf16(r.x, r.y);
        packed.y = pack_bf16(r.z, r.w);
        *(uint2*)&Qb[i] = packed;
    } else if (which == 1) {
        uint2 packed;
        packed.x = pack_bf16(r.x, r.y);
        packed.y = pack_bf16(r.z, r.w);
        *(uint2*)&Kb[i] = packed;
        float4 ivv = *(const float4*)&iv[col];
        float dot = r.x * ivv.x + r.y * ivv.y + r.z * ivv.z + r.w * ivv.w;
        #pragma unroll
        for (int o = 16; o > 0; o >>= 1)
            dot += __shfl_xor_sync(0xffffffffu, dot, o);
        if (lane == 0) maskv[row] = 1.f / (1.f + expf(-dot));
    } else {
        vt[col + 0][w] = __float2bfloat16(r.x);
        vt[col + 1][w] = __float2bfloat16(r.y);
        vt[col + 2][w] = __float2bfloat16(r.z);
        vt[col + 3][w] = __float2bfloat16(r.w);
        __syncthreads();
        if (t < 128) {
            __nv_bfloat16 tmp[8];
            #pragma unroll
            for (int k = 0; k < 8; k++) tmp[k] = vt[t][k];
            *(uint4*)&Vtb[(size_t)t * S + blockIdx.x * 8] = *(uint4*)tmp;
        }
    }
}

// ---------------- flash attention, FA2, 64-row q-tile, 4 warps, 2 CTA/SM -----
#define FLASH_SMEM_BYTES (22400 * 4)
__global__ void __launch_bounds__(128, 2)
flash_kernel(const __nv_bfloat16* __restrict__ Qb, const __nv_bfloat16* __restrict__ Kb,
             const __nv_bfloat16* __restrict__ Vtb, const float* __restrict__ maskv,
             __nv_bfloat16* __restrict__ Opart, float* __restrict__ mpart,
             float* __restrict__ lpart) {
    extern __shared__ uint32_t smu[];
    uint32_t* Qs   = smu;               // 64*68  = 4352
    uint32_t* KsB  = smu + 4352;        // 2*4352
    uint32_t* VTsB = smu + 13056;       // 2*4608
    float* msk = (float*)(smu + 22272); // 2*64

    const int tid  = threadIdx.x;
    const int lane = tid & 31, w = tid >> 5;
    const int g    = lane >> 2, tig = lane & 3;
    const int wm   = w * 16;

    const int l7    = lane & 7;
    const int lrow8 = (lane >> 3) & 1;
    const int lcol4 = (lane >> 4) * 4;
    const int quad  = lane >> 3;
    const int brow  = (quad >= 2) ? 8 : 0;
    const int bcol  = (quad & 1) * 4;

    const int qbase  = blockIdx.x * 64;
    const int split  = blockIdx.y;
    const int kstart = split * (S / 4);
    const int NT     = (S / 4) / 64;

    auto fillKV = [&](int st, int kb) {
        #pragma unroll
        for (int i = 0; i < 8; i++) {
            int ci = i * 128 + tid;
            int kr = ci >> 4, kch = (ci & 15);
            cp16(KsB + st * 4352 + kr * 68 + kch * 4,
                 Kb + (size_t)(kb + kr) * HIDD + kch * 8);
            int vr = ci >> 3, vch = (ci & 7);
            cp16(VTsB + st * 4608 + vr * 36 + vch * 4,
                 Vtb + (size_t)vr * S + kb + vch * 8);
        }
        if (tid < 16) cp16(msk + st * 64 + tid * 4, maskv + kb + tid * 4);
    };

    #pragma unroll
    for (int i = 0; i < 8; i++) {
        int ci = i * 128 + tid;
        int r = ci >> 4, ch = (ci & 15);
        cp16(Qs + r * 68 + ch * 4, Qb + (size_t)(qbase + r) * HIDD + ch * 8);
    }
    CP_COMMIT();
    fillKV(0, kstart);
    CP_COMMIT();
    asm volatile("cp.async.wait_group 1;\n" ::: "memory");
    __syncthreads();

    uint32_t qf[8][4];
    {
        const int qrow = wm + l7 + 8 * lrow8;
        #pragma unroll
        for (int kt = 0; kt < 8; kt++)
            ldsm_x4(qf[kt][0], qf[kt][1], qf[kt][2], qf[kt][3],
                    saddr(&Qs[qrow * 68 + kt * 8 + lcol4]));
    }

    float o_acc[16][4] = {};
    float m0 = -1e30f, m1 = -1e30f, l0 = 0.f, l1 = 0.f;

    for (int t = 0; t < NT; t++) {
        const int st = t & 1;
        if (t + 1 < NT) fillKV(st ^ 1, kstart + (t + 1) * 64);
        CP_COMMIT();
        CP_WAIT1();
        __syncthreads();

        const uint32_t* Ks  = KsB + st * 4352;
        const uint32_t* VTs = VTsB + st * 4608;
        const float* mk = msk + st * 64;

        float s_acc[8][4] = {};
        #pragma unroll
        for (int kt = 0; kt < 8; kt++) {
            uint32_t b[8][2];
            #pragma unroll
            for (int nb = 0; nb < 4; nb++)
                ldsm_x4(b[2 * nb][0], b[2 * nb][1], b[2 * nb + 1][0], b[2 * nb + 1][1],
                        saddr(&Ks[(nb * 16 + brow + l7) * 68 + kt * 8 + bcol]));
            #pragma unroll
            for (int nf = 0; nf < 8; nf++)
                mma_bf16(s_acc[nf], qf[kt][0], qf[kt][1], qf[kt][2], qf[kt][3],
                         b[nf][0], b[nf][1]);
        }

        float rmax0 = -1e30f, rmax1 = -1e30f;
        #pragma unroll
        for (int nf = 0; nf < 8; nf++) {
            const int cc = nf * 8 + 2 * tig;
            const float mk0 = mk[cc] * 0.015625f, mk1 = mk[cc + 1] * 0.015625f;
            s_acc[nf][0] *= mk0; s_acc[nf][1] *= mk1;
            s_acc[nf][2] *= mk0; s_acc[nf][3] *= mk1;
            rmax0 = fmaxf(rmax0, fmaxf(s_acc[nf][0], s_acc[nf][1]));
            rmax1 = fmaxf(rmax1, fmaxf(s_acc[nf][2], s_acc[nf][3]));
        }
        #pragma unroll
        for (int o = 1; o <= 2; o <<= 1) {
            rmax0 = fmaxf(rmax0, __shfl_xor_sync(0xffffffffu, rmax0, o));
            rmax1 = fmaxf(rmax1, __shfl_xor_sync(0xffffffffu, rmax1, o));
        }
        const float mn0 = fmaxf(m0, rmax0), mn1 = fmaxf(m1, rmax1);
        const float c0 = __expf(m0 - mn0), c1 = __expf(m1 - mn1);
        m0 = mn0; m1 = mn1;

        uint32_t pa[4][4];
        float ps0 = 0.f, ps1 = 0.f;
        #pragma unroll
        for (int k2 = 0; k2 < 4; k2++) {
            float p00 = __expf(s_acc[2 * k2][0] - mn0), p01 = __expf(s_acc[2 * k2][1] - mn0);
            float p02 = __expf(s_acc[2 * k2][2] - mn1), p03 = __expf(s_acc[2 * k2][3] - mn1);
            float p10 = __expf(s_acc[2 * k2 + 1][0] - mn0), p11 = __expf(s_acc[2 * k2 + 1][1] - mn0);
            float p12 = __expf(s_acc[2 * k2 + 1][2] - mn1), p13 = __expf(s_acc[2 * k2 + 1][3] - mn1);
            ps0 += p00 + p01 + p10 + p11;
            ps1 += p02 + p03 + p12 + p13;
            pa[k2][0] = pack_bf16(p00, p01);
            pa[k2][1] = pack_bf16(p02, p03);
            pa[k2][2] = pack_bf16(p10, p11);
            pa[k2][3] = pack_bf16(p12, p13);
        }
        #pragma unroll
        for (int o = 1; o <= 2; o <<= 1) {
            ps0 += __shfl_xor_sync(0xffffffffu, ps0, o);
            ps1 += __shfl_xor_sync(0xffffffffu, ps1, o);
        }
        l0 = l0 * c0 + ps0;
        l1 = l1 * c1 + ps1;

        #pragma unroll
        for (int nf = 0; nf < 16; nf++) {
            o_acc[nf][0] *= c0; o_acc[nf][1] *= c0;
            o_acc[nf][2] *= c1; o_acc[nf][3] *= c1;
        }

        #pragma unroll
        for (int k2 = 0; k2 < 4; k2++) {
            #pragma unroll
            for (int np = 0; np < 8; np++) {
                uint32_t b0, b1, b2, b3;
                ldsm_x4(b0, b1, b2, b3,
                        saddr(&VTs[(np * 16 + brow + l7) * 36 + k2 * 8 + bcol]));
                mma_bf16(o_acc[2 * np],     pa[k2][0], pa[k2][1], pa[k2][2], pa[k2][3], b0, b1);
                mma_bf16(o_acc[2 * np + 1], pa[k2][0], pa[k2][1], pa[k2][2], pa[k2][3], b2, b3);
            }
        }
        __syncthreads();
    }

    __nv_bfloat16* Ob = Opart + ((size_t)split * S + qbase) * HIDD;
    const int row0 = wm + g, row1 = wm + g + 8;
    #pragma unroll
    for (int nf = 0; nf < 16; nf++) {
        const int cc = nf * 8 + 2 * tig;
        *(uint32_t*)&Ob[(size_t)row0 * HIDD + cc] = pack_bf16(o_acc[nf][0], o_acc[nf][1]);
        *(uint32_t*)&Ob[(size_t)row1 * HIDD + cc] = pack_bf16(o_acc[nf][2], o_acc[nf][3]);
    }
    if (tig == 0) {
        mpart[split * S + qbase + row0] = m0;
        lpart[split * S + qbase + row0] = l0;
        mpart[split * S + qbase + row1] = m1;
        lpart[split * S + qbase + row1] = l1;
    }
}

// ---------------- combine the 4 KV-split partials -> bf16 av (vectorized) ----
// grid 2048, 256 thr: 2 rows/block, each thread does 4 cols via uint2.
__global__ void combine_kernel(const __nv_bfloat16* __restrict__ Opart,
                               const float* __restrict__ mpart,
                               const float* __restrict__ lpart,
                               __nv_bfloat16* __restrict__ avb) {
    const int t = threadIdx.x;
    const int row = blockIdx.x * 2 + (t >> 7);   // 128 thr per row
    const int col = (t & 127);                   // not used directly; 32 col-chunks
    const int c4  = (t & 31) * 4;
    if ((t & 127) >= 32) return;                 // 32 active chunk-threads per row
    float M = -1e30f;
    #pragma unroll
    for (int z = 0; z < 4; z++) M = fmaxf(M, mpart[z * S + row]);
    float denom = 0.f;
    float acc[4] = {};
    #pragma unroll
    for (int z = 0; z < 4; z++) {
        const float e = __expf(mpart[z * S + row] - M);
        denom += e * lpart[z * S + row];
        uint2 u = *(const uint2*)&Opart[((size_t)z * S + row) * HIDD + c4];
        float2 lo = unpack_bf16(u.x), hi = unpack_bf16(u.y);
        acc[0] += e * lo.x; acc[1] += e * lo.y;
        acc[2] += e * hi.x; acc[3] += e * hi.y;
    }
    const float inv = 1.f / denom;
    uint2 packed;
    packed.x = pack_bf16(acc[0] * inv, acc[1] * inv);
    packed.y = pack_bf16(acc[2] * inv, acc[3] * inv);
    *(uint2*)&avb[(size_t)row * HIDD + c4] = packed;
    (void)col;
}

// ---------------- fused w + per-row + global LN stats (one block) ------------
__global__ void stats_kernel(const float* __restrict__ sa_p, const float* __restrict__ sq_p,
                             const float* __restrict__ sd_p, const float* __restrict__ cidp,
                             float* __restrict__ wrow) {
    __shared__ float rc[1024], rc2[1024];
    __shared__ double rs[1024], rq[1024];
    float s = 0.f, q = 0.f;
    for (int i = threadIdx.x; i < CDIM; i += 1024) {
        float v = cidp[i];
        s += v; q += v * v;
    }
    rc[threadIdx.x] = s; rc2[threadIdx.x] = q; __syncthreads();
    for (int o = 512; o > 0; o >>= 1) {
        if (threadIdx.x < o) { rc[threadIdx.x] += rc[threadIdx.x + o]; rc2[threadIdx.x] += rc2[threadIdx.x + o]; }
        __syncthreads();
    }
    const float sc = rc[0], sc2 = rc2[0];
    __syncthreads();
    double ds = 0.0, dq = 0.0;
    for (int row = threadIdx.x; row < S; row += 1024) {
        float sa = 0.f, sq = 0.f, sd = 0.f;
        #pragma unroll
        for (int nb = 0; nb < 10; nb++) {
            sa += sa_p[nb * S + row];
            sq += sq_p[nb * S + row];
            sd += sd_p[nb * S + row];
        }
        const float wv = 1.f / (1.f + expf(-sd));
        wrow[row] = wv;
        ds += (double)(sa - wv * sc);
        dq += (double)(sq - 2.f * wv * sd + wv * wv * sc2);
    }
    rs[threadIdx.x] = ds; rq[threadIdx.x] = dq; __syncthreads();
    for (int o = 512; o > 0; o >>= 1) {
        if (threadIdx.x < o) { rs[threadIdx.x] += rs[threadIdx.x + o]; rq[threadIdx.x] += rq[threadIdx.x + o]; }
        __syncthreads();
    }
    if (threadIdx.x == 0) {
        double n = (double)S * (double)CDIM;
        double mean = rs[0] / n;
        double var  = rq[0] / n - mean * mean;
        g_mean_f = (float)mean;
        g_rstd_f = (float)rsqrt(var + 1e-5);
    }
}

// ---------------- apply decoupling + normalize + transpose -------------------
__global__ void out_transpose_kernel(const float* __restrict__ att,
                                     const float* __restrict__ wrow,
                                     const float* __restrict__ cidp,
                                     float* __restrict__ out) {
    __shared__ float tile[32][33];
    __shared__ float ws[32];
    float mean = g_mean_f, rstd = g_rstd_f;
    int c0 = blockIdx.x * 32, s0 = blockIdx.y * 32;
    if (threadIdx.y == 0) ws[threadIdx.x] = wrow[s0 + threadIdx.x];
    #pragma unroll
    for (int i = threadIdx.y; i < 32; i += 8)
        tile[i][threadIdx.x] = att[(size_t)(s0 + i) * CDIM + c0 + threadIdx.x];
    __syncthreads();
    #pragma unroll
    for (int i = threadIdx.y; i < 32; i += 8) {
        const float cv = cidp[c0 + i];
        out[(size_t)(c0 + i) * S + s0 + threadIdx.x] =
            (tile[threadIdx.x][i] - ws[threadIdx.x] * cv - mean) * rstd;
    }
}

// ---------------- launch ------------------------------------------------------
extern "C" void kernel_launch(void* const* d_in, const int* in_sizes, int n_in,
                              void* d_out, int out_size) {
    const float* z      = (const float*)d_in[0];
    const float* cid    = (const float*)d_in[1];
    const float* mlp_w  = (const float*)d_in[2];
    const float* mlp_b  = (const float*)d_in[3];
    const float* proj_w = (const float*)d_in[4];
    const float* proj_b = (const float*)d_in[5];
    const float* wq_w   = (const float*)d_in[6];
    const float* wq_b   = (const float*)d_in[7];
    const float* wk_w   = (const float*)d_in[8];
    const float* wk_b   = (const float*)d_in[9];
    const float* wv_w   = (const float*)d_in[10];
    const float* wv_b   = (const float*)d_in[11];
    const float* wo_w   = (const float*)d_in[12];
    const float* wo_b   = (const float*)d_in[13];
    float* out = (float*)d_out;

    float *tmean, *trstd, *iv, *cidp, *maskv, *mpart, *lpart, *att;
    float *wo_sa, *wo_sq, *wo_sd, *wrow;
    __nv_bfloat16 *ztb, *wqb, *wkb, *wvb, *wob, *Qb, *Kb, *Vtb, *avb, *qkvp, *Opart;
    cudaGetSymbolAddress((void**)&tmean, g_tmean);
    cudaGetSymbolAddress((void**)&trstd, g_trstd);
    cudaGetSymbolAddress((void**)&ztb,   g_ztb);
    cudaGetSymbolAddress((void**)&wqb,   g_wqb);
    cudaGetSymbolAddress((void**)&wkb,   g_wkb);
    cudaGetSymbolAddress((void**)&wvb,   g_wvb);
    cudaGetSymbolAddress((void**)&wob,   g_wob);
    cudaGetSymbolAddress((void**)&Qb,    g_Qb);
    cudaGetSymbolAddress((void**)&Kb,    g_Kb);
    cudaGetSymbolAddress((void**)&Vtb,   g_Vtb);
    cudaGetSymbolAddress((void**)&iv,    g_iv);
    cudaGetSymbolAddress((void**)&cidp,  g_cidp);
    cudaGetSymbolAddress((void**)&maskv, g_maskv);
    cudaGetSymbolAddress((void**)&qkvp,  g_qkvp);
    cudaGetSymbolAddress((void**)&Opart, g_Opart);
    cudaGetSymbolAddress((void**)&mpart, g_mpart);
    cudaGetSymbolAddress((void**)&lpart, g_lpart);
    cudaGetSymbolAddress((void**)&avb,   g_avb);
    cudaGetSymbolAddress((void**)&att,   g_att);
    cudaGetSymbolAddress((void**)&wo_sa, g_wo_sa);
    cudaGetSymbolAddress((void**)&wo_sq, g_wo_sq);
    cudaGetSymbolAddress((void**)&wo_sd, g_wo_sd);
    cudaGetSymbolAddress((void**)&wrow,  g_wrow);

    static int s_attr_set = 0;
    if (!s_attr_set) {
        cudaFuncSetAttribute(flash_kernel, cudaFuncAttributeMaxDynamicSharedMemorySize,
                             FLASH_SMEM_BYTES);
        s_attr_set = 1;
    }

    dim3 t32x8(32, 8);

    // 1. prep: token LN stats + weight convert + iv/cidp (one launch)
    prep_kernel<<<2176, 256>>>(z, tmean, trstd,
                               wq_w, wk_w, wv_w, wo_w, wqb, wkb, wvb, wob,
                               mlp_w, mlp_b, proj_w, proj_b, cid, iv, cidp);
    // 2. fused normalize + transpose -> bf16 tokens
    norm_transpose_kernel<<<dim3(S / 32, CDIM / 32), t32x8>>>(z, tmean, trstd, ztb);
    // 3. QKV bf16 mma, split-K x4, bf16 partials
    qkv_mma_kernel<<<dim3(1, S / 128, 12), 256>>>(ztb, wqb, wkb, wvb, qkvp);
    // 4. reduce partials + bias -> Q/K bf16 + Vt, fused mask
    reduce_qkv_kernel<<<dim3(512, 3), 256>>>(qkvp, wq_b, wk_b, wv_b, iv,
                                             Qb, Kb, Vtb, maskv);
    // 5. flash attention (R14 config: 64-row q-tile, 4 warps, 2 CTA/SM)
    flash_kernel<<<dim3(S / 64, 4), 128, FLASH_SMEM_BYTES>>>(
        Qb, Kb, Vtb, maskv, Opart, mpart, lpart);
    // 6. combine splits -> bf16 av (vectorized)
    combine_kernel<<<S / 2, 256>>>(Opart, mpart, lpart, avb);
    // 7. attended = av wo^T + wo_b, fused per-row stats partials
    wo_mma_kernel<<<dim3(CDIM / 128, S / 128), 256>>>(avb, wob, wo_b, cidp, att,
                                                      wo_sa, wo_sq, wo_sd);
    // 8. fused w + per-row + global LN stats (one block)
    stats_kernel<<<1, 1024>>>(wo_sa, wo_sq, wo_sd, cidp, wrow);
    // 9. decoupling + normalize + transpose to (C,H,W)
    out_transpose_kernel<<<dim3(CDIM / 32, S / 32), t32x8>>>(att, wrow, cidp, out);
}

// round 17
// speedup vs baseline: 1.0151x; 1.0029x over previous
#include <cuda_runtime.h>
#include <cuda_bf16.h>
#include <math.h>
#include <stdint.h>

#define S     4096
#define CDIM  1280
#define HIDD  128
#define DID   1536
#define EPSV  1e-5f

// ---------------- scratch (static device globals; no allocations) ----------
__device__ float          g_tmean[S];
__device__ float          g_trstd[S];
__device__ __nv_bfloat16  g_ztb [(size_t)S * CDIM];
__device__ __nv_bfloat16  g_wqb [(size_t)HIDD * CDIM];
__device__ __nv_bfloat16  g_wkb [(size_t)HIDD * CDIM];
__device__ __nv_bfloat16  g_wvb [(size_t)HIDD * CDIM];
__device__ __nv_bfloat16  g_wob [(size_t)CDIM * HIDD];
__device__ __nv_bfloat16  g_Qb  [(size_t)S * HIDD];
__device__ __nv_bfloat16  g_Kb  [(size_t)S * HIDD];
__device__ __nv_bfloat16  g_Vtb [(size_t)HIDD * S];
__device__ float          g_iv  [HIDD];
__device__ float          g_cidp[CDIM];
__device__ float          g_maskv[S];
__device__ __nv_bfloat16  g_qkvp[(size_t)12 * S * HIDD];
__device__ __nv_bfloat16  g_Opart[(size_t)4 * S * HIDD];
__device__ float          g_mpart[4 * S];
__device__ float          g_lpart[4 * S];
__device__ __nv_bfloat16  g_avb [(size_t)S * HIDD];
__device__ float          g_att [(size_t)S * CDIM];
__device__ float          g_wo_sa[10 * S];
__device__ float          g_wo_sq[10 * S];
__device__ float          g_wo_sd[10 * S];
__device__ float          g_wrow[S];
__device__ float          g_mean_f;
__device__ float          g_rstd_f;

// ---------------- helpers ----------------------------------------------------
__device__ __forceinline__ void cp16(void* dst, const void* src) {
    uint32_t d = (uint32_t)__cvta_generic_to_shared(dst);
    asm volatile("cp.async.cg.shared.global [%0], [%1], 16;\n" :: "r"(d), "l"(src));
}
#define CP_COMMIT() asm volatile("cp.async.commit_group;\n" ::: "memory")
#define CP_WAIT1()  asm volatile("cp.async.wait_group 1;\n" ::: "memory")
#define CP_WAIT2()  asm volatile("cp.async.wait_group 2;\n" ::: "memory")

__device__ __forceinline__ uint32_t saddr(const void* p) {
    return (uint32_t)__cvta_generic_to_shared(p);
}

__device__ __forceinline__ void ldsm_x4(uint32_t& r0, uint32_t& r1, uint32_t& r2,
                                        uint32_t& r3, uint32_t a) {
    asm volatile("ldmatrix.sync.aligned.m8n8.x4.shared.b16 {%0,%1,%2,%3}, [%4];"
                 : "=r"(r0), "=r"(r1), "=r"(r2), "=r"(r3) : "r"(a));
}

__device__ __forceinline__ void mma_bf16(float* d,
        uint32_t a0, uint32_t a1, uint32_t a2, uint32_t a3,
        uint32_t b0, uint32_t b1) {
    asm volatile(
        "mma.sync.aligned.m16n8k16.row.col.f32.bf16.bf16.f32 "
        "{%0,%1,%2,%3}, {%4,%5,%6,%7}, {%8,%9}, {%0,%1,%2,%3};"
        : "+f"(d[0]), "+f"(d[1]), "+f"(d[2]), "+f"(d[3])
        : "r"(a0), "r"(a1), "r"(a2), "r"(a3), "r"(b0), "r"(b1));
}

__device__ __forceinline__ uint32_t pack_bf16(float x, float y) {
    __nv_bfloat162 t = __floats2bfloat162_rn(x, y);
    return *reinterpret_cast<uint32_t*>(&t);
}

__device__ __forceinline__ float2 unpack_bf16(uint32_t u) {
    __nv_bfloat162 t = *reinterpret_cast<__nv_bfloat162*>(&u);
    return make_float2(__bfloat162float(t.x), __bfloat162float(t.y));
}

// ---------------- prep: token LN stats + weight convert + dual matvec --------
__global__ void prep_kernel(const float* __restrict__ z,
                            float* __restrict__ tmean, float* __restrict__ trstd,
                            const float* __restrict__ wq, const float* __restrict__ wk,
                            const float* __restrict__ wv, const float* __restrict__ wo,
                            __nv_bfloat16* qb, __nv_bfloat16* kb,
                            __nv_bfloat16* vb, __nv_bfloat16* ob,
                            const float* __restrict__ w1, const float* __restrict__ b1,
                            const float* __restrict__ w2, const float* __restrict__ b2,
                            const float* __restrict__ x,
                            float* __restrict__ o1, float* __restrict__ o2) {
    __shared__ float ssum[8][33], ssq[8][33];
    __shared__ float sm[256];
    const int blk = blockIdx.x;
    if (blk < 128) {
        const int tok0 = blk * 32;
        const int tok = threadIdx.x & 31, stripe = threadIdx.x >> 5;
        float s = 0.f, q = 0.f;
        for (int c = stripe; c < CDIM; c += 8) {
            float v = z[(size_t)c * S + tok0 + tok];
            s += v; q += v * v;
        }
        ssum[stripe][tok] = s; ssq[stripe][tok] = q;
        __syncthreads();
        if (threadIdx.x < 32) {
            float st = 0.f, qt = 0.f;
            #pragma unroll
            for (int k = 0; k < 8; k++) { st += ssum[k][threadIdx.x]; qt += ssq[k][threadIdx.x]; }
            float mean = st / CDIM;
            float var  = qt / CDIM - mean * mean;
            tmean[tok0 + threadIdx.x] = mean;
            trstd[tok0 + threadIdx.x] = rsqrtf(var + EPSV);
        }
    } else if (blk < 768) {
        const int j = blk - 128;
        const int which = j / 160;
        const int base = (j % 160) * 1024;
        const float* src; __nv_bfloat16* dst;
        if (which == 0)      { src = wq; dst = qb; }
        else if (which == 1) { src = wk; dst = kb; }
        else if (which == 2) { src = wv; dst = vb; }
        else                 { src = wo; dst = ob; }
        #pragma unroll
        for (int r = 0; r < 4; r++) {
            int i = base + r * 256 + threadIdx.x;
            dst[i] = __float2bfloat16(src[i]);
        }
    } else {
        const int n = blk - 768;
        const float* w; float bv; float* o; int nn;
        if (n < HIDD) { nn = n;        w = w1 + (size_t)nn * DID; bv = b1[nn]; o = o1; }
        else          { nn = n - HIDD; w = w2 + (size_t)nn * DID; bv = b2[nn]; o = o2; }
        const float4* w4 = (const float4*)w;
        const float4* x4 = (const float4*)x;
        float s = 0.f;
        for (int k = threadIdx.x; k < DID / 4; k += 256) {
            float4 wv4 = w4[k], xv = x4[k];
            s += wv4.x * xv.x + wv4.y * xv.y + wv4.z * xv.z + wv4.w * xv.w;
        }
        sm[threadIdx.x] = s; __syncthreads();
        for (int off = 128; off > 0; off >>= 1) {
            if (threadIdx.x < off) sm[threadIdx.x] += sm[threadIdx.x + off];
            __syncthreads();
        }
        if (threadIdx.x == 0) o[nn] = sm[0] + bv;
    }
}

// ---------------- fused normalize + transpose: z (C,S) -> ztb (S,C) bf16 -----
__global__ void norm_transpose_kernel(const float* __restrict__ z,
                                      const float* __restrict__ tmean,
                                      const float* __restrict__ trstd,
                                      __nv_bfloat16* __restrict__ ztb) {
    __shared__ float tile[32][33];
    int s0 = blockIdx.x * 32, c0 = blockIdx.y * 32;
    #pragma unroll
    for (int i = threadIdx.y; i < 32; i += 8)
        tile[i][threadIdx.x] = z[(size_t)(c0 + i) * S + s0 + threadIdx.x];
    __syncthreads();
    #pragma unroll
    for (int i = threadIdx.y; i < 32; i += 8) {
        const int tok = s0 + i;
        const float mean = tmean[tok], rstd = trstd[tok];
        ztb[(size_t)tok * CDIM + c0 + threadIdx.x] =
            __float2bfloat16((tile[threadIdx.x][i] - mean) * rstd);
    }
}

// ---------------- bf16 mma GEMM engine (128x128, BT, ldmatrix, 3-stage) ------
__device__ __forceinline__ void bf16_gemm_body_bout(
        const __nv_bfloat16* __restrict__ A, const __nv_bfloat16* __restrict__ B,
        __nv_bfloat16* __restrict__ Cb,
        int N, int K, int kstart, int nkt, int m0, int n0) {
    __shared__ uint32_t As[3][128][12];
    __shared__ uint32_t Bs[3][128][12];

    const int tid  = threadIdx.x;
    const int lane = tid & 31, wid = tid >> 5;
    const int g    = lane >> 2, tig = lane & 3;
    const int wm   = (wid >> 2) * 64;
    const int wn   = (wid & 3) * 32;

    const int l7    = lane & 7;
    const int lrow8 = (lane >> 3) & 1;
    const int lcol4 = (lane >> 4) * 4;
    const int quad  = lane >> 3;
    const int brow  = (quad >= 2) ? 8 : 0;
    const int bcol  = (quad & 1) * 4;

    const int fr = tid >> 1, fc = (tid & 1);

    float acc[4][4][4] = {};

    auto fill = [&](int s, int k0) {
        cp16(&As[s][fr][fc * 4], A + (size_t)(m0 + fr) * K + k0 + fc * 8);
        cp16(&Bs[s][fr][fc * 4], B + (size_t)(n0 + fr) * K + k0 + fc * 8);
    };

    fill(0, kstart);
    CP_COMMIT();
    fill(1, kstart + 16);
    CP_COMMIT();

    int st = 0;
    for (int t = 0; t < nkt; t++) {
        if (t + 2 < nkt) fill((st + 2) % 3, kstart + (t + 2) * 16);
        CP_COMMIT();
        CP_WAIT2();
        __syncthreads();

        uint32_t a[4][4], b[4][2];
        #pragma unroll
        for (int mf = 0; mf < 4; mf++)
            ldsm_x4(a[mf][0], a[mf][1], a[mf][2], a[mf][3],
                    saddr(&As[st][wm + mf * 16 + l7 + 8 * lrow8][lcol4]));
        ldsm_x4(b[0][0], b[0][1], b[1][0], b[1][1],
                saddr(&Bs[st][wn + brow + l7][bcol]));
        ldsm_x4(b[2][0], b[2][1], b[3][0], b[3][1],
                saddr(&Bs[st][wn + 16 + brow + l7][bcol]));
        #pragma unroll
        for (int mf = 0; mf < 4; mf++)
            #pragma unroll
            for (int nf = 0; nf < 4; nf++)
                mma_bf16(acc[mf][nf], a[mf][0], a[mf][1], a[mf][2], a[mf][3],
                         b[nf][0], b[nf][1]);
        __syncthreads();
        st = (st + 1) % 3;
    }

    #pragma unroll
    for (int mf = 0; mf < 4; mf++) {
        #pragma unroll
        for (int nf = 0; nf < 4; nf++) {
            const int r0 = m0 + wm + mf * 16 + g;
            const int c  = n0 + wn + nf * 8 + 2 * tig;
            *(uint32_t*)&Cb[(size_t)r0 * N + c]       = pack_bf16(acc[mf][nf][0], acc[mf][nf][1]);
            *(uint32_t*)&Cb[(size_t)(r0 + 8) * N + c] = pack_bf16(acc[mf][nf][2], acc[mf][nf][3]);
        }
    }
}

// Fused QKV split-K x4 -> bf16 partials: grid (1, 32, 12); z = which*4 + split.
__global__ __launch_bounds__(256, 2)
void qkv_mma_kernel(const __nv_bfloat16* __restrict__ A,
                    const __nv_bfloat16* __restrict__ wq, const __nv_bfloat16* __restrict__ wk,
                    const __nv_bfloat16* __restrict__ wv, __nv_bfloat16* __restrict__ qkvp) {
    const int which = blockIdx.z >> 2;
    const int split = blockIdx.z & 3;
    const __nv_bfloat16* B = (which == 0) ? wq : (which == 1) ? wk : wv;
    __nv_bfloat16* out = qkvp + (size_t)blockIdx.z * S * HIDD;
    bf16_gemm_body_bout(A, B, out, HIDD, CDIM, split * 320, 20,
                        blockIdx.y * 128, blockIdx.x * 128);
}

// WO GEMM with fused decoupling-stats epilogue, 3-stage. grid (10, 32).
__global__ __launch_bounds__(256, 2)
void wo_mma_kernel(const __nv_bfloat16* __restrict__ A, const __nv_bfloat16* __restrict__ B,
                   const float* __restrict__ bias, const float* __restrict__ cidp,
                   float* __restrict__ C,
                   float* __restrict__ sa_p, float* __restrict__ sq_p,
                   float* __restrict__ sd_p) {
    __shared__ uint32_t As[3][128][12];
    __shared__ uint32_t Bs[3][128][12];
    __shared__ float ssa[4][128], ssq2[4][128], ssd[4][128];

    const int N = CDIM, K = HIDD;
    const int m0 = blockIdx.y * 128, n0 = blockIdx.x * 128;
    const int tid  = threadIdx.x;
    const int lane = tid & 31, wid = tid >> 5;
    const int g    = lane >> 2, tig = lane & 3;
    const int wm   = (wid >> 2) * 64;
    const int wn   = (wid & 3) * 32;

    const int l7    = lane & 7;
    const int lrow8 = (lane >> 3) & 1;
    const int lcol4 = (lane >> 4) * 4;
    const int quad  = lane >> 3;
    const int brow  = (quad >= 2) ? 8 : 0;
    const int bcol  = (quad & 1) * 4;

    const int fr = tid >> 1, fc = (tid & 1);

    float acc[4][4][4] = {};

    auto fill = [&](int s, int k0) {
        cp16(&As[s][fr][fc * 4], A + (size_t)(m0 + fr) * K + k0 + fc * 8);
        cp16(&Bs[s][fr][fc * 4], B + (size_t)(n0 + fr) * K + k0 + fc * 8);
    };

    fill(0, 0);
    CP_COMMIT();
    fill(1, 16);
    CP_COMMIT();

    const int nkt = 8;
    int st = 0;
    for (int t = 0; t < nkt; t++) {
        if (t + 2 < nkt) fill((st + 2) % 3, (t + 2) * 16);
        CP_COMMIT();
        CP_WAIT2();
        __syncthreads();

        uint32_t a[4][4], b[4][2];
        #pragma unroll
        for (int mf = 0; mf < 4; mf++)
            ldsm_x4(a[mf][0], a[mf][1], a[mf][2], a[mf][3],
                    saddr(&As[st][wm + mf * 16 + l7 + 8 * lrow8][lcol4]));
        ldsm_x4(b[0][0], b[0][1], b[1][0], b[1][1],
                saddr(&Bs[st][wn + brow + l7][bcol]));
        ldsm_x4(b[2][0], b[2][1], b[3][0], b[3][1],
                saddr(&Bs[st][wn + 16 + brow + l7][bcol]));
        #pragma unroll
        for (int mf = 0; mf < 4; mf++)
            #pragma unroll
            for (int nf = 0; nf < 4; nf++)
                mma_bf16(acc[mf][nf], a[mf][0], a[mf][1], a[mf][2], a[mf][3],
                         b[nf][0], b[nf][1]);
        __syncthreads();
        st = (st + 1) % 3;
    }

    float tsa[4][2] = {}, tsq[4][2] = {}, tsd[4][2] = {};
    #pragma unroll
    for (int mf = 0; mf < 4; mf++) {
        #pragma unroll
        for (int nf = 0; nf < 4; nf++) {
            const int r0 = m0 + wm + mf * 16 + g;
            const int c  = n0 + wn + nf * 8 + 2 * tig;
            float b0 = bias[c], b1 = bias[c + 1];
            float c0v = cidp[c], c1v = cidp[c + 1];
            float2 v0 = make_float2(acc[mf][nf][0] + b0, acc[mf][nf][1] + b1);
            float2 v1 = make_float2(acc[mf][nf][2] + b0, acc[mf][nf][3] + b1);
            *(float2*)&C[(size_t)r0 * N + c]       = v0;
            *(float2*)&C[(size_t)(r0 + 8) * N + c] = v1;
            tsa[mf][0] += v0.x + v0.y;
            tsa[mf][1] += v1.x + v1.y;
            tsq[mf][0] += v0.x * v0.x + v0.y * v0.y;
            tsq[mf][1] += v1.x * v1.x + v1.y * v1.y;
            tsd[mf][0] += v0.x * c0v + v0.y * c1v;
            tsd[mf][1] += v1.x * c0v + v1.y * c1v;
        }
    }
    #pragma unroll
    for (int mf = 0; mf < 4; mf++) {
        #pragma unroll
        for (int h = 0; h < 2; h++) {
            float a0 = tsa[mf][h], q0 = tsq[mf][h], d0 = tsd[mf][h];
            #pragma unroll
            for (int o = 1; o <= 2; o <<= 1) {
                a0 += __shfl_xor_sync(0xffffffffu, a0, o);
                q0 += __shfl_xor_sync(0xffffffffu, q0, o);
                d0 += __shfl_xor_sync(0xffffffffu, d0, o);
            }
            if (tig == 0) {
                const int row = wm + mf * 16 + g + h * 8;
                const int cb = wid & 3;
                ssa[cb][row] = a0; ssq2[cb][row] = q0; ssd[cb][row] = d0;
            }
        }
    }
    __syncthreads();
    if (tid < 128) {
        float a0 = ssa[0][tid] + ssa[1][tid] + ssa[2][tid] + ssa[3][tid];
        float q0 = ssq2[0][tid] + ssq2[1][tid] + ssq2[2][tid] + ssq2[3][tid];
        float d0 = ssd[0][tid] + ssd[1][tid] + ssd[2][tid] + ssd[3][tid];
        const int grow = m0 + tid;
        sa_p[blockIdx.x * S + grow] = a0;
        sq_p[blockIdx.x * S + grow] = q0;
        sd_p[blockIdx.x * S + grow] = d0;
    }
}

// Reduce bf16 QKV partials x4 (+bias) -> bf16 Q/K + Vt; fused mask.
__global__ void reduce_qkv_kernel(const __nv_bfloat16* __restrict__ qkvp,
                                  const float* __restrict__ bq, const float* __restrict__ bk,
                                  const float* __restrict__ bv,
                                  const float* __restrict__ iv,
                                  __nv_bfloat16* __restrict__ Qb, __nv_bfloat16* __restrict__ Kb,
                                  __nv_bfloat16* __restrict__ Vtb,
                                  float* __restrict__ maskv) {
    __shared__ __nv_bfloat16 vt[128][10];
    const size_t MN = (size_t)S * HIDD;
    const int which = blockIdx.y;
    const int t = threadIdx.x;
    const int lane = t & 31, w = t >> 5;
    const int row = blockIdx.x * 8 + w;
    const int col = lane * 4;
    size_t i = ((size_t)blockIdx.x * 256 + t) * 4;

    const __nv_bfloat16* base = qkvp + (size_t)which * 4 * MN;
    float4 r = make_float4(0.f, 0.f, 0.f, 0.f);
    #pragma unroll
    for (int zp = 0; zp < 4; zp++) {
        uint2 u = *(const uint2*)&base[(size_t)zp * MN + i];
        float2 lo = unpack_bf16(u.x), hi = unpack_bf16(u.y);
        r.x += lo.x; r.y += lo.y; r.z += hi.x; r.w += hi.y;
    }
    const float* bias = (which == 0) ? bq : (which == 1) ? bk : bv;
    float4 bb = *(const float4*)&bias[col];
    r.x += bb.x; r.y += bb.y; r.z += bb.z; r.w += bb.w;

    if (which == 0) {
        uint2 packed;
        packed.x = pack_bf16(r.x, r.y);
        packed.y = pack_bf16(r.z, r.w);
        *(uint2*)&Qb[i] = packed;
    } else if (which == 1) {
        uint2 packed;
        packed.x = pack_bf16(r.x, r.y);
        packed.y = pack_bf16(r.z, r.w);
        *(uint2*)&Kb[i] = packed;
        float4 ivv = *(const float4*)&iv[col];
        float dot = r.x * ivv.x + r.y * ivv.y + r.z * ivv.z + r.w * ivv.w;
        #pragma unroll
        for (int o = 16; o > 0; o >>= 1)
            dot += __shfl_xor_sync(0xffffffffu, dot, o);
        if (lane == 0) maskv[row] = 1.f / (1.f + expf(-dot));
    } else {
        vt[col + 0][w] = __float2bfloat16(r.x);
        vt[col + 1][w] = __float2bfloat16(r.y);
        vt[col + 2][w] = __float2bfloat16(r.z);
        vt[col + 3][w] = __float2bfloat16(r.w);
        __syncthreads();
        if (t < 128) {
            __nv_bfloat16 tmp[8];
            #pragma unroll
            for (int k = 0; k < 8; k++) tmp[k] = vt[t][k];
            *(uint4*)&Vtb[(size_t)t * S + blockIdx.x * 8] = *(uint4*)tmp;
        }
    }
}

// ---------------- flash attention, FA2, 64-row q-tile, 4 warps, 2 CTA/SM -----
#define FLASH_SMEM_BYTES (22400 * 4)
__global__ void __launch_bounds__(128, 2)
flash_kernel(const __nv_bfloat16* __restrict__ Qb, const __nv_bfloat16* __restrict__ Kb,
             const __nv_bfloat16* __restrict__ Vtb, const float* __restrict__ maskv,
             __nv_bfloat16* __restrict__ Opart, float* __restrict__ mpart,
             float* __restrict__ lpart) {
    extern __shared__ uint32_t smu[];
    uint32_t* Qs   = smu;               // 64*68  = 4352
    uint32_t* KsB  = smu + 4352;        // 2*4352
    uint32_t* VTsB = smu + 13056;       // 2*4608
    float* msk = (float*)(smu + 22272); // 2*64

    const int tid  = threadIdx.x;
    const int lane = tid & 31, w = tid >> 5;
    const int g    = lane >> 2, tig = lane & 3;
    const int wm   = w * 16;

    const int l7    = lane & 7;
    const int lrow8 = (lane >> 3) & 1;
    const int lcol4 = (lane >> 4) * 4;
    const int quad  = lane >> 3;
    const int brow  = (quad >= 2) ? 8 : 0;
    const int bcol  = (quad & 1) * 4;

    const int qbase  = blockIdx.x * 64;
    const int split  = blockIdx.y;
    const int kstart = split * (S / 4);
    const int NT     = (S / 4) / 64;

    auto fillKV = [&](int st, int kb) {
        #pragma unroll
        for (int i = 0; i < 8; i++) {
            int ci = i * 128 + tid;
            int kr = ci >> 4, kch = (ci & 15);
            cp16(KsB + st * 4352 + kr * 68 + kch * 4,
                 Kb + (size_t)(kb + kr) * HIDD + kch * 8);
            int vr = ci >> 3, vch = (ci & 7);
            cp16(VTsB + st * 4608 + vr * 36 + vch * 4,
                 Vtb + (size_t)vr * S + kb + vch * 8);
        }
        if (tid < 16) cp16(msk + st * 64 + tid * 4, maskv + kb + tid * 4);
    };

    #pragma unroll
    for (int i = 0; i < 8; i++) {
        int ci = i * 128 + tid;
        int r = ci >> 4, ch = (ci & 15);
        cp16(Qs + r * 68 + ch * 4, Qb + (size_t)(qbase + r) * HIDD + ch * 8);
    }
    CP_COMMIT();
    fillKV(0, kstart);
    CP_COMMIT();
    asm volatile("cp.async.wait_group 1;\n" ::: "memory");
    __syncthreads();

    uint32_t qf[8][4];
    {
        const int qrow = wm + l7 + 8 * lrow8;
        #pragma unroll
        for (int kt = 0; kt < 8; kt++)
            ldsm_x4(qf[kt][0], qf[kt][1], qf[kt][2], qf[kt][3],
                    saddr(&Qs[qrow * 68 + kt * 8 + lcol4]));
    }

    float o_acc[16][4] = {};
    float m0 = -1e30f, m1 = -1e30f, l0 = 0.f, l1 = 0.f;

    for (int t = 0; t < NT; t++) {
        const int st = t & 1;
        if (t + 1 < NT) fillKV(st ^ 1, kstart + (t + 1) * 64);
        CP_COMMIT();
        CP_WAIT1();
        __syncthreads();

        const uint32_t* Ks  = KsB + st * 4352;
        const uint32_t* VTs = VTsB + st * 4608;
        const float* mk = msk + st * 64;

        float s_acc[8][4] = {};
        #pragma unroll
        for (int kt = 0; kt < 8; kt++) {
            uint32_t b[8][2];
            #pragma unroll
            for (int nb = 0; nb < 4; nb++)
                ldsm_x4(b[2 * nb][0], b[2 * nb][1], b[2 * nb + 1][0], b[2 * nb + 1][1],
                        saddr(&Ks[(nb * 16 + brow + l7) * 68 + kt * 8 + bcol]));
            #pragma unroll
            for (int nf = 0; nf < 8; nf++)
                mma_bf16(s_acc[nf], qf[kt][0], qf[kt][1], qf[kt][2], qf[kt][3],
                         b[nf][0], b[nf][1]);
        }

        float rmax0 = -1e30f, rmax1 = -1e30f;
        #pragma unroll
        for (int nf = 0; nf < 8; nf++) {
            const int cc = nf * 8 + 2 * tig;
            const float mk0 = mk[cc] * 0.015625f, mk1 = mk[cc + 1] * 0.015625f;
            s_acc[nf][0] *= mk0; s_acc[nf][1] *= mk1;
            s_acc[nf][2] *= mk0; s_acc[nf][3] *= mk1;
            rmax0 = fmaxf(rmax0, fmaxf(s_acc[nf][0], s_acc[nf][1]));
            rmax1 = fmaxf(rmax1, fmaxf(s_acc[nf][2], s_acc[nf][3]));
        }
        #pragma unroll
        for (int o = 1; o <= 2; o <<= 1) {
            rmax0 = fmaxf(rmax0, __shfl_xor_sync(0xffffffffu, rmax0, o));
            rmax1 = fmaxf(rmax1, __shfl_xor_sync(0xffffffffu, rmax1, o));
        }
        const float mn0 = fmaxf(m0, rmax0), mn1 = fmaxf(m1, rmax1);
        const float c0 = __expf(m0 - mn0), c1 = __expf(m1 - mn1);
        m0 = mn0; m1 = mn1;

        uint32_t pa[4][4];
        float ps0 = 0.f, ps1 = 0.f;
        #pragma unroll
        for (int k2 = 0; k2 < 4; k2++) {
            float p00 = __expf(s_acc[2 * k2][0] - mn0), p01 = __expf(s_acc[2 * k2][1] - mn0);
            float p02 = __expf(s_acc[2 * k2][2] - mn1), p03 = __expf(s_acc[2 * k2][3] - mn1);
            float p10 = __expf(s_acc[2 * k2 + 1][0] - mn0), p11 = __expf(s_acc[2 * k2 + 1][1] - mn0);
            float p12 = __expf(s_acc[2 * k2 + 1][2] - mn1), p13 = __expf(s_acc[2 * k2 + 1][3] - mn1);
            ps0 += p00 + p01 + p10 + p11;
            ps1 += p02 + p03 + p12 + p13;
            pa[k2][0] = pack_bf16(p00, p01);
            pa[k2][1] = pack_bf16(p02, p03);
            pa[k2][2] = pack_bf16(p10, p11);
            pa[k2][3] = pack_bf16(p12, p13);
        }
        #pragma unroll
        for (int o = 1; o <= 2; o <<= 1) {
            ps0 += __shfl_xor_sync(0xffffffffu, ps0, o);
            ps1 += __shfl_xor_sync(0xffffffffu, ps1, o);
        }
        l0 = l0 * c0 + ps0;
        l1 = l1 * c1 + ps1;

        #pragma unroll
        for (int nf = 0; nf < 16; nf++) {
            o_acc[nf][0] *= c0; o_acc[nf][1] *= c0;
            o_acc[nf][2] *= c1; o_acc[nf][3] *= c1;
        }

        #pragma unroll
        for (int k2 = 0; k2 < 4; k2++) {
            #pragma unroll
            for (int np = 0; np < 8; np++) {
                uint32_t b0, b1, b2, b3;
                ldsm_x4(b0, b1, b2, b3,
                        saddr(&VTs[(np * 16 + brow + l7) * 36 + k2 * 8 + bcol]));
                mma_bf16(o_acc[2 * np],     pa[k2][0], pa[k2][1], pa[k2][2], pa[k2][3], b0, b1);
                mma_bf16(o_acc[2 * np + 1], pa[k2][0], pa[k2][1], pa[k2][2], pa[k2][3], b2, b3);
            }
        }
        __syncthreads();
    }

    __nv_bfloat16* Ob = Opart + ((size_t)split * S + qbase) * HIDD;
    const int row0 = wm + g, row1 = wm + g + 8;
    #pragma unroll
    for (int nf = 0; nf < 16; nf++) {
        const int cc = nf * 8 + 2 * tig;
        *(uint32_t*)&Ob[(size_t)row0 * HIDD + cc] = pack_bf16(o_acc[nf][0], o_acc[nf][1]);
        *(uint32_t*)&Ob[(size_t)row1 * HIDD + cc] = pack_bf16(o_acc[nf][2], o_acc[nf][3]);
    }
    if (tig == 0) {
        mpart[split * S + qbase + row0] = m0;
        lpart[split * S + qbase + row0] = l0;
        mpart[split * S + qbase + row1] = m1;
        lpart[split * S + qbase + row1] = l1;
    }
}

// ---------------- combine the 4 KV-split partials -> bf16 av -----------------
// grid 512, 256 thr, all active: 8 rows/CTA, 32 chunk-threads/row, 4 cols each.
__global__ void combine_kernel(const __nv_bfloat16* __restrict__ Opart,
                               const float* __restrict__ mpart,
                               const float* __restrict__ lpart,
                               __nv_bfloat16* __restrict__ avb) {
    const int t = threadIdx.x;
    const int row = blockIdx.x * 8 + (t >> 5);
    const int c4  = (t & 31) * 4;
    float M = -1e30f;
    #pragma unroll
    for (int z = 0; z < 4; z++) M = fmaxf(M, mpart[z * S + row]);
    float denom = 0.f;
    float acc[4] = {};
    #pragma unroll
    for (int z = 0; z < 4; z++) {
        const float e = __expf(mpart[z * S + row] - M);
        denom += e * lpart[z * S + row];
        uint2 u = *(const uint2*)&Opart[((size_t)z * S + row) * HIDD + c4];
        float2 lo = unpack_bf16(u.x), hi = unpack_bf16(u.y);
        acc[0] += e * lo.x; acc[1] += e * lo.y;
        acc[2] += e * hi.x; acc[3] += e * hi.y;
    }
    const float inv = 1.f / denom;
    uint2 packed;
    packed.x = pack_bf16(acc[0] * inv, acc[1] * inv);
    packed.y = pack_bf16(acc[2] * inv, acc[3] * inv);
    *(uint2*)&avb[(size_t)row * HIDD + c4] = packed;
}

// ---------------- fused w + per-row + global LN stats (one block) ------------
__global__ void stats_kernel(const float* __restrict__ sa_p, const float* __restrict__ sq_p,
                             const float* __restrict__ sd_p, const float* __restrict__ cidp,
                             float* __restrict__ wrow) {
    __shared__ float rc[1024], rc2[1024];
    __shared__ double rs[1024], rq[1024];
    float s = 0.f, q = 0.f;
    for (int i = threadIdx.x; i < CDIM; i += 1024) {
        float v = cidp[i];
        s += v; q += v * v;
    }
    rc[threadIdx.x] = s; rc2[threadIdx.x] = q; __syncthreads();
    for (int o = 512; o > 0; o >>= 1) {
        if (threadIdx.x < o) { rc[threadIdx.x] += rc[threadIdx.x + o]; rc2[threadIdx.x] += rc2[threadIdx.x + o]; }
        __syncthreads();
    }
    const float sc = rc[0], sc2 = rc2[0];
    __syncthreads();
    double ds = 0.0, dq = 0.0;
    for (int row = threadIdx.x; row < S; row += 1024) {
        float sa = 0.f, sq = 0.f, sd = 0.f;
        #pragma unroll
        for (int nb = 0; nb < 10; nb++) {
            sa += sa_p[nb * S + row];
            sq += sq_p[nb * S + row];
            sd += sd_p[nb * S + row];
        }
        const float wv = 1.f / (1.f + expf(-sd));
        wrow[row] = wv;
        ds += (double)(sa - wv * sc);
        dq += (double)(sq - 2.f * wv * sd + wv * wv * sc2);
    }
    rs[threadIdx.x] = ds; rq[threadIdx.x] = dq; __syncthreads();
    for (int o = 512; o > 0; o >>= 1) {
        if (threadIdx.x < o) { rs[threadIdx.x] += rs[threadIdx.x + o]; rq[threadIdx.x] += rq[threadIdx.x + o]; }
        __syncthreads();
    }
    if (threadIdx.x == 0) {
        double n = (double)S * (double)CDIM;
        double mean = rs[0] / n;
        double var  = rq[0] / n - mean * mean;
        g_mean_f = (float)mean;
        g_rstd_f = (float)rsqrt(var + 1e-5);
    }
}

// ---------------- apply decoupling + normalize + transpose -------------------
__global__ void out_transpose_kernel(const float* __restrict__ att,
                                     const float* __restrict__ wrow,
                                     const float* __restrict__ cidp,
                                     float* __restrict__ out) {
    __shared__ float tile[32][33];
    __shared__ float ws[32];
    float mean = g_mean_f, rstd = g_rstd_f;
    int c0 = blockIdx.x * 32, s0 = blockIdx.y * 32;
    if (threadIdx.y == 0) ws[threadIdx.x] = wrow[s0 + threadIdx.x];
    #pragma unroll
    for (int i = threadIdx.y; i < 32; i += 8)
        tile[i][threadIdx.x] = att[(size_t)(s0 + i) * CDIM + c0 + threadIdx.x];
    __syncthreads();
    #pragma unroll
    for (int i = threadIdx.y; i < 32; i += 8) {
        const float cv = cidp[c0 + i];
        out[(size_t)(c0 + i) * S + s0 + threadIdx.x] =
            (tile[threadIdx.x][i] - ws[threadIdx.x] * cv - mean) * rstd;
    }
}

// ---------------- launch ------------------------------------------------------
extern "C" void kernel_launch(void* const* d_in, const int* in_sizes, int n_in,
                              void* d_out, int out_size) {
    const float* z      = (const float*)d_in[0];
    const float* cid    = (const float*)d_in[1];
    const float* mlp_w  = (const float*)d_in[2];
    const float* mlp_b  = (const float*)d_in[3];
    const float* proj_w = (const float*)d_in[4];
    const float* proj_b = (const float*)d_in[5];
    const float* wq_w   = (const float*)d_in[6];
    const float* wq_b   = (const float*)d_in[7];
    const float* wk_w   = (const float*)d_in[8];
    const float* wk_b   = (const float*)d_in[9];
    const float* wv_w   = (const float*)d_in[10];
    const float* wv_b   = (const float*)d_in[11];
    const float* wo_w   = (const float*)d_in[12];
    const float* wo_b   = (const float*)d_in[13];
    float* out = (float*)d_out;

    float *tmean, *trstd, *iv, *cidp, *maskv, *mpart, *lpart, *att;
    float *wo_sa, *wo_sq, *wo_sd, *wrow;
    __nv_bfloat16 *ztb, *wqb, *wkb, *wvb, *wob, *Qb, *Kb, *Vtb, *avb, *qkvp, *Opart;
    cudaGetSymbolAddress((void**)&tmean, g_tmean);
    cudaGetSymbolAddress((void**)&trstd, g_trstd);
    cudaGetSymbolAddress((void**)&ztb,   g_ztb);
    cudaGetSymbolAddress((void**)&wqb,   g_wqb);
    cudaGetSymbolAddress((void**)&wkb,   g_wkb);
    cudaGetSymbolAddress((void**)&wvb,   g_wvb);
    cudaGetSymbolAddress((void**)&wob,   g_wob);
    cudaGetSymbolAddress((void**)&Qb,    g_Qb);
    cudaGetSymbolAddress((void**)&Kb,    g_Kb);
    cudaGetSymbolAddress((void**)&Vtb,   g_Vtb);
    cudaGetSymbolAddress((void**)&iv,    g_iv);
    cudaGetSymbolAddress((void**)&cidp,  g_cidp);
    cudaGetSymbolAddress((void**)&maskv, g_maskv);
    cudaGetSymbolAddress((void**)&qkvp,  g_qkvp);
    cudaGetSymbolAddress((void**)&Opart, g_Opart);
    cudaGetSymbolAddress((void**)&mpart, g_mpart);
    cudaGetSymbolAddress((void**)&lpart, g_lpart);
    cudaGetSymbolAddress((void**)&avb,   g_avb);
    cudaGetSymbolAddress((void**)&att,   g_att);
    cudaGetSymbolAddress((void**)&wo_sa, g_wo_sa);
    cudaGetSymbolAddress((void**)&wo_sq, g_wo_sq);
    cudaGetSymbolAddress((void**)&wo_sd, g_wo_sd);
    cudaGetSymbolAddress((void**)&wrow,  g_wrow);

    static int s_attr_set = 0;
    if (!s_attr_set) {
        cudaFuncSetAttribute(flash_kernel, cudaFuncAttributeMaxDynamicSharedMemorySize,
                             FLASH_SMEM_BYTES);
        s_attr_set = 1;
    }

    dim3 t32x8(32, 8);

    // 1. prep: token LN stats + weight convert + iv/cidp (one launch)
    prep_kernel<<<2176, 256>>>(z, tmean, trstd,
                               wq_w, wk_w, wv_w, wo_w, wqb, wkb, wvb, wob,
                               mlp_w, mlp_b, proj_w, proj_b, cid, iv, cidp);
    // 2. fused normalize + transpose -> bf16 tokens
    norm_transpose_kernel<<<dim3(S / 32, CDIM / 32), t32x8>>>(z, tmean, trstd, ztb);
    // 3. QKV bf16 mma, split-K x4, bf16 partials (3-stage pipeline)
    qkv_mma_kernel<<<dim3(1, S / 128, 12), 256>>>(ztb, wqb, wkb, wvb, qkvp);
    // 4. reduce partials + bias -> Q/K bf16 + Vt, fused mask
    reduce_qkv_kernel<<<dim3(512, 3), 256>>>(qkvp, wq_b, wk_b, wv_b, iv,
                                             Qb, Kb, Vtb, maskv);
    // 5. flash attention (measured-best config)
    flash_kernel<<<dim3(S / 64, 4), 128, FLASH_SMEM_BYTES>>>(
        Qb, Kb, Vtb, maskv, Opart, mpart, lpart);
    // 6. combine splits -> bf16 av (full-occupancy)
    combine_kernel<<<S / 8, 256>>>(Opart, mpart, lpart, avb);
    // 7. attended = av wo^T + wo_b, fused per-row stats (3-stage pipeline)
    wo_mma_kernel<<<dim3(CDIM / 128, S / 128), 256>>>(avb, wob, wo_b, cidp, att,
                                                      wo_sa, wo_sq, wo_sd);
    // 8. fused w + per-row + global LN stats
    stats_kernel<<<1, 1024>>>(wo_sa, wo_sq, wo_sd, cidp, wrow);
    // 9. decoupling + normalize + transpose to (C,H,W)
    out_transpose_kernel<<<dim3(CDIM / 32, S / 32), t32x8>>>(att, wrow, cidp, out);
}